// round 4
// baseline (speedup 1.0000x reference)
#include <cuda_runtime.h>
#include <math.h>

#define NB 4
#define NN 2048
#define DD 128
#define KK 32
#define H1 530      // 2*EIN
#define H1P 544     // padded to 17*32
#define NBI (NB*NN) // 8192

// ---------------- scratch (static device globals; zero-initialized) -------------
__device__ float g_A  [NBI * H1];        // feats_i @ W1[0:128]
__device__ float g_Bv [NBI * H1P + 64];  // feats_j @ W1[128:256], padded stride+tail
__device__ float g_NH [NBI * 256];       // feats   @ node_w1[0:128]
__device__ float g_cm [NBI * 3];         // mean-centered coords
__device__ int   g_nbidx[NBI * KK];
__device__ float g_dk   [NBI * KK];

// ---------------- fast SiLU: FMA-pipe Taylor sigmoid, MUFU fallback -------------
__device__ __forceinline__ float silu_f(float x) {
    float ax = fabsf(x);
    if (ax < 1.0f) {
        float x2 = x * x;
        float s = 31.0f / 1451520.0f;
        s = fmaf(s, x2, -17.0f / 80640.0f);
        s = fmaf(s, x2,  1.0f / 480.0f);
        s = fmaf(s, x2, -1.0f / 48.0f);
        s = fmaf(s, x2,  0.25f);
        return x * fmaf(x, s, 0.5f);
    }
    return x / (1.0f + __expf(-x));
}

// ---------------- mean-center coords ----------------
__global__ void __launch_bounds__(256) k_mean(const float* __restrict__ coors) {
    int b = blockIdx.x, t = threadIdx.x;
    __shared__ float rx[256], ry[256], rz[256];
    const float* cb = coors + (size_t)b * NN * 3;
    float sx = 0.f, sy = 0.f, sz = 0.f;
    for (int j = t; j < NN; j += 256) {
        sx += cb[3 * j]; sy += cb[3 * j + 1]; sz += cb[3 * j + 2];
    }
    rx[t] = sx; ry[t] = sy; rz[t] = sz;
    __syncthreads();
    for (int s = 128; s > 0; s >>= 1) {
        if (t < s) { rx[t] += rx[t + s]; ry[t] += ry[t + s]; rz[t] += rz[t + s]; }
        __syncthreads();
    }
    float mx = rx[0] * (1.0f / NN), my = ry[0] * (1.0f / NN), mz = rz[0] * (1.0f / NN);
    float* cmb = g_cm + (size_t)b * NN * 3;
    for (int j = t; j < NN; j += 256) {
        cmb[3 * j]     = cb[3 * j]     - mx;
        cmb[3 * j + 1] = cb[3 * j + 1] - my;
        cmb[3 * j + 2] = cb[3 * j + 2] - mz;
    }
}

// ---------------- precompute A = F@W1a, Bv = F@W1b (8 nodes / warp) --------------
__global__ void __launch_bounds__(256) k_precompAB(const float* __restrict__ feats,
                                                   const float* __restrict__ ew1) {
    int n0 = blockIdx.x * 64;
    __shared__ float sf[64 * 128];
    int t = threadIdx.x;
    #pragma unroll 4
    for (int idx = t; idx < 64 * 128; idx += 256) sf[idx] = feats[(size_t)n0 * 128 + idx];
    __syncthreads();
    int ng = t >> 5, lane = t & 31;
    const float2* fq[8];
    #pragma unroll
    for (int q = 0; q < 8; q++) fq[q] = (const float2*)(sf + (ng * 8 + q) * 128);
    for (int cc = 0; cc < H1; cc += 32) {
        int c = cc + lane;
        int cs = (c < H1) ? c : (H1 - 1);
        float a[8], bb[8];
        #pragma unroll
        for (int q = 0; q < 8; q++) { a[q] = 0.f; bb[q] = 0.f; }
        #pragma unroll 2
        for (int dd = 0; dd < 64; dd++) {
            float wA0 = ew1[(size_t)(2 * dd) * H1 + cs];
            float wA1 = ew1[(size_t)(2 * dd + 1) * H1 + cs];
            float wB0 = ew1[(size_t)(128 + 2 * dd) * H1 + cs];
            float wB1 = ew1[(size_t)(129 + 2 * dd) * H1 + cs];
            #pragma unroll
            for (int q = 0; q < 8; q++) {
                float2 fv = fq[q][dd];
                a[q]  = fmaf(fv.x, wA0, a[q]);  a[q]  = fmaf(fv.y, wA1, a[q]);
                bb[q] = fmaf(fv.x, wB0, bb[q]); bb[q] = fmaf(fv.y, wB1, bb[q]);
            }
        }
        if (c < H1) {
            #pragma unroll
            for (int q = 0; q < 8; q++) {
                int node = n0 + ng * 8 + q;
                g_A [(size_t)node * H1  + c] = a[q];
                g_Bv[(size_t)node * H1P + c] = bb[q];
            }
        }
    }
}

// ---------------- precompute NH = F @ node_w1[0:128] ----------------------------
__global__ void __launch_bounds__(256) k_precompNH(const float* __restrict__ feats,
                                                   const float* __restrict__ nw1) {
    int n0 = blockIdx.x * 64;
    __shared__ float sf[64 * 128];
    int t = threadIdx.x;
    #pragma unroll 4
    for (int idx = t; idx < 64 * 128; idx += 256) sf[idx] = feats[(size_t)n0 * 128 + idx];
    __syncthreads();
    int ng = t >> 5, lane = t & 31;
    const float2* fq[8];
    #pragma unroll
    for (int q = 0; q < 8; q++) fq[q] = (const float2*)(sf + (ng * 8 + q) * 128);
    for (int cc = 0; cc < 256; cc += 32) {
        int c = cc + lane;
        float a[8];
        #pragma unroll
        for (int q = 0; q < 8; q++) a[q] = 0.f;
        #pragma unroll 2
        for (int dd = 0; dd < 64; dd++) {
            float w0 = nw1[(size_t)(2 * dd) * 256 + c];
            float w1 = nw1[(size_t)(2 * dd + 1) * 256 + c];
            #pragma unroll
            for (int q = 0; q < 8; q++) {
                float2 fv = fq[q][dd];
                a[q] = fmaf(fv.x, w0, a[q]); a[q] = fmaf(fv.y, w1, a[q]);
            }
        }
        #pragma unroll
        for (int q = 0; q < 8; q++)
            g_NH[(size_t)(n0 + ng * 8 + q) * 256 + c] = a[q];
    }
}

// ---------------- top-K: binary search on float bit-keys in registers ------------
__global__ void __launch_bounds__(256) k_topk(const float* __restrict__ coors) {
    int bi = blockIdx.x;
    int b  = bi >> 11;
    int t = threadIdx.x, lane = t & 31, wid = t >> 5;
    __shared__ int s_cnt[8];
    __shared__ unsigned s_loS, s_hiS, s_thr;
    __shared__ int s_done, s_sel, s_curmin;

    const float* cb = coors + (size_t)b * NN * 3;
    float cx = coors[(size_t)bi * 3], cy = coors[(size_t)bi * 3 + 1], cz = coors[(size_t)bi * 3 + 2];
    float d[8]; unsigned ud[8];
    #pragma unroll
    for (int i = 0; i < 8; i++) {
        int j = t + i * 256;
        float dx = cx - cb[3 * j], dy = cy - cb[3 * j + 1], dz = cz - cb[3 * j + 2];
        float dv = dx * dx + dy * dy + dz * dz;
        d[i] = dv; ud[i] = __float_as_uint(dv);
    }
    if (t == 0) { s_loS = 0u; s_hiS = 0x7f800000u; s_done = 0; s_sel = 0; s_curmin = -1; }
    __syncthreads();

    #pragma unroll 1
    for (int it = 0; it < 34; it++) {
        unsigned lo = s_loS, hi = s_hiS;
        unsigned mid = lo + ((hi - lo) >> 1);
        int c = 0;
        #pragma unroll
        for (int i = 0; i < 8; i++) c += (ud[i] <= mid) ? 1 : 0;
        #pragma unroll
        for (int off = 16; off; off >>= 1) c += __shfl_xor_sync(0xffffffffu, c, off);
        if (lane == 0) s_cnt[wid] = c;
        __syncthreads();
        if (t == 0) {
            int tot = 0;
            #pragma unroll
            for (int w = 0; w < 8; w++) tot += s_cnt[w];
            if (tot == KK) { s_thr = mid; s_done = 1; }
            else {
                unsigned nlo = lo, nhi = hi;
                if (tot > KK) nhi = mid; else nlo = mid + 1;
                if (nlo >= nhi) { s_thr = nlo; s_done = 2; }
                s_loS = nlo; s_hiS = nhi;
            }
        }
        __syncthreads();
        if (s_done) break;
    }
    unsigned thr = s_thr; int mode = s_done;

    // definite members
    #pragma unroll
    for (int i = 0; i < 8; i++) {
        bool sel = (mode == 1) ? (ud[i] <= thr) : (ud[i] < thr);
        if (sel) {
            int p = atomicAdd(&s_sel, 1);
            g_nbidx[(size_t)bi * KK + p] = t + i * 256;
            g_dk   [(size_t)bi * KK + p] = d[i];
        }
    }
    __syncthreads();
    if (mode == 2) {  // ties at boundary key: fill with smallest indices
        int C = s_sel;
        for (int k = C; k < KK; k++) {
            int prev = s_curmin;
            int cand = 0x7fffffff;
            #pragma unroll
            for (int i = 0; i < 8; i++) {
                int j = t + i * 256;
                if (ud[i] == thr && j > prev && j < cand) cand = j;
            }
            #pragma unroll
            for (int off = 16; off; off >>= 1) {
                int o = __shfl_xor_sync(0xffffffffu, cand, off);
                cand = min(cand, o);
            }
            if (lane == 0) s_cnt[wid] = cand;
            __syncthreads();
            if (t == 0) {
                int mn = s_cnt[0];
                #pragma unroll
                for (int w = 1; w < 8; w++) mn = min(mn, s_cnt[w]);
                g_nbidx[(size_t)bi * KK + k] = mn;
                g_dk   [(size_t)bi * KK + k] = __uint_as_float(thr);
                s_curmin = mn;
            }
            __syncthreads();
        }
    }
}

// ---------------- reduce-scatter step for 64 partials over 32 lanes --------------
template <int MASK, int HALF>
__device__ __forceinline__ void rstep(float* pr, int lane) {
    bool hi = (lane & MASK) != 0;
    #pragma unroll
    for (int i = 0; i < HALF; i++) {
        float sent = hi ? pr[i] : pr[HALF + i];
        float recv = __shfl_xor_sync(0xffffffffu, sent, MASK);
        pr[i] = (hi ? pr[HALF + i] : pr[i]) + recv;
    }
}

// ---------------- fused edge MLP + coord update + node MLP ----------------------
__global__ void __launch_bounds__(256) k_main(
    const float* __restrict__ feats, const float* __restrict__ coors,
    const float* __restrict__ ew1,  const float* __restrict__ eb1,
    const float* __restrict__ ew2,  const float* __restrict__ eb2,
    const float* __restrict__ cw1g, const float* __restrict__ cb1g,
    const float* __restrict__ cw2g, const float* __restrict__ cb2g,
    const float* __restrict__ xw1g, const float* __restrict__ xb1g,
    const float* __restrict__ xw2g, const float* __restrict__ xb2g,
    const float* __restrict__ nw1,  const float* __restrict__ nb1,
    const float* __restrict__ nw2,  const float* __restrict__ nb2,
    float* __restrict__ out)
{
    extern __shared__ float smx[];
    float* s_base = smx;                     // 544
    float* s_w1c  = s_base + H1P;            // 9*544
    float* s_w2t  = s_w1c + 9 * H1P;         // 16*544
    float* s_cw1  = s_w2t + 16 * H1P;        // 1024
    float* s_xw1  = s_cw1 + 1024;            // 1024
    float* s_cb1  = s_xw1 + 1024;            // 64
    float* s_xb1  = s_cb1 + 64;              // 64
    float* s_cw2  = s_xb1 + 64;              // 64
    float* s_xw2  = s_cw2 + 64;              // 64
    float* s_b2   = s_xw2 + 64;              // 16
    float* s_enc  = s_b2 + 16;               // 288
    float* s_m    = s_enc + 288;             // 8*64
    float* s_maccw= s_m + 512;               // 8*16
    float* s_macc = s_maccw + 128;           // 16
    float* s_cacc = s_macc + 16;             // 4
    float* s_geo  = s_cacc + 4;              // 8
    float* s_hid  = s_geo + 8;               // 256
    float* s_out0 = s_hid + 256;             // 128
    float* s_out1 = s_out0 + 128;            // 128
    int*   s_nb   = (int*)(s_out1 + 128);    // 32

    int tid = threadIdx.x;
    int bi  = blockIdx.x;
    int b   = bi >> 11;

    for (int c = tid; c < H1P; c += 256)
        s_base[c] = (c < H1) ? (g_A[(size_t)bi * H1 + c] + eb1[c]) : 0.f;
    for (int idx = tid; idx < 9 * H1P; idx += 256) {
        int r = idx / H1P, c = idx - r * H1P;
        s_w1c[idx] = (c < H1) ? ew1[(256 + r) * H1 + c] : 0.f;
    }
    for (int idx = tid; idx < 16 * H1P; idx += 256) {
        int c = idx / H1P, el = idx - c * H1P;
        s_w2t[idx] = (el < H1) ? ew2[el * 16 + c] : 0.f;
    }
    for (int idx = tid; idx < 1024; idx += 256) { s_cw1[idx] = cw1g[idx]; s_xw1[idx] = xw1g[idx]; }
    if (tid < 64) { s_cb1[tid] = cb1g[tid]; s_xb1[tid] = xb1g[tid]; s_cw2[tid] = cw2g[tid]; s_xw2[tid] = xw2g[tid]; }
    if (tid < 16) s_b2[tid] = eb2[tid];
    if (tid < 4)  s_cacc[tid] = 0.f;
    if (tid < 32) {
        float dv = g_dk[(size_t)bi * KK + tid];
        s_enc[tid * 9 + 0] = sinf(dv);
        s_enc[tid * 9 + 1] = sinf(0.5f * dv);
        s_enc[tid * 9 + 2] = sinf(0.25f * dv);
        s_enc[tid * 9 + 3] = sinf(0.125f * dv);
        s_enc[tid * 9 + 4] = cosf(dv);
        s_enc[tid * 9 + 5] = cosf(0.5f * dv);
        s_enc[tid * 9 + 6] = cosf(0.25f * dv);
        s_enc[tid * 9 + 7] = cosf(0.125f * dv);
        s_enc[tid * 9 + 8] = dv;
        s_nb[tid] = g_nbidx[(size_t)bi * KK + tid];
    }
    if (tid < 3) { s_geo[tid] = coors[(size_t)bi * 3 + tid]; s_geo[3 + tid] = g_cm[(size_t)bi * 3 + tid]; }
    __syncthreads();

    int lane = tid & 31, wid = tid >> 5;
    float cb2r = cb2g[0], xb2r = xb2g[0];
    float ci0 = s_geo[0], ci1 = s_geo[1], ci2 = s_geo[2];
    float ai0 = s_geo[3], ai1 = s_geo[4], ai2 = s_geo[5];
    const float* cb3 = coors + (size_t)b * NN * 3;
    const float* cmb = g_cm  + (size_t)b * NN * 3;

    // ---- 4 edges per warp, processed together through the chunk loop ----
    float pr[64];
    #pragma unroll
    for (int i = 0; i < 64; i++) pr[i] = 0.f;

    int jn[4];
    const float* bvp[4];
    float e9[4][9];
    #pragma unroll
    for (int e = 0; e < 4; e++) {
        int j = s_nb[wid * 4 + e];
        jn[e] = j;
        bvp[e] = g_Bv + ((size_t)b * NN + j) * H1P;
        #pragma unroll
        for (int r = 0; r < 9; r++) e9[e][r] = s_enc[(wid * 4 + e) * 9 + r];
    }
    float bvc[4];
    #pragma unroll
    for (int e = 0; e < 4; e++) bvc[e] = bvp[e][lane];

    #pragma unroll 2
    for (int tt = 0; tt < 17; tt++) {
        int el = tt * 32 + lane;
        float bvn[4];
        #pragma unroll
        for (int e = 0; e < 4; e++) bvn[e] = bvp[e][el + 32];  // tail pad covers overrun
        float base = s_base[el];
        float w1r[9];
        #pragma unroll
        for (int r = 0; r < 9; r++) w1r[r] = s_w1c[r * H1P + el];
        float w2r[16];
        #pragma unroll
        for (int c = 0; c < 16; c++) w2r[c] = s_w2t[c * H1P + el];
        #pragma unroll
        for (int e = 0; e < 4; e++) {
            float acc = base + bvc[e];
            #pragma unroll
            for (int r = 0; r < 9; r++) acc = fmaf(e9[e][r], w1r[r], acc);
            float h = silu_f(acc);
            #pragma unroll
            for (int c = 0; c < 16; c++) pr[e * 16 + c] = fmaf(h, w2r[c], pr[e * 16 + c]);
        }
        #pragma unroll
        for (int e = 0; e < 4; e++) bvc[e] = bvn[e];
    }

    // reduce-scatter: lane ends with totals for ids 2*lane, 2*lane+1 (id = e*16+c)
    rstep<16, 32>(pr, lane);
    rstep<8, 16>(pr, lane);
    rstep<4, 8>(pr, lane);
    rstep<2, 4>(pr, lane);
    rstep<1, 2>(pr, lane);

    {
        int id0 = lane * 2;
        int c0 = id0 & 15;
        float m0 = silu_f(pr[0] + s_b2[c0]);
        float m1 = silu_f(pr[1] + s_b2[c0 + 1]);
        s_m[wid * 64 + id0]     = m0;
        s_m[wid * 64 + id0 + 1] = m1;
    }
    __syncwarp();
    if (lane < 16) {
        float* mm = s_m + wid * 64;
        s_maccw[wid * 16 + lane] = mm[lane] + mm[16 + lane] + mm[32 + lane] + mm[48 + lane];
    }
    __syncwarp();

    // coor MLPs + geometry per edge
    float cb1l0 = s_cb1[lane], cb1l1 = s_cb1[lane + 32];
    float xb1l0 = s_xb1[lane], xb1l1 = s_xb1[lane + 32];
    float cw2l0 = s_cw2[lane], cw2l1 = s_cw2[lane + 32];
    float xw2l0 = s_xw2[lane], xw2l1 = s_xw2[lane + 32];
    float caccl = 0.f;

    #pragma unroll 1
    for (int e = 0; e < 4; e++) {
        const float* mm = s_m + wid * 64 + e * 16;
        float hA0 = cb1l0, hA1 = cb1l1, hX0 = xb1l0, hX1 = xb1l1;
        #pragma unroll
        for (int c = 0; c < 16; c++) {
            float mv = mm[c];
            hA0 = fmaf(mv, s_cw1[c * 64 + lane],      hA0);
            hA1 = fmaf(mv, s_cw1[c * 64 + lane + 32], hA1);
            hX0 = fmaf(mv, s_xw1[c * 64 + lane],      hX0);
            hX1 = fmaf(mv, s_xw1[c * 64 + lane + 32], hX1);
        }
        hA0 = silu_f(hA0); hA1 = silu_f(hA1); hX0 = silu_f(hX0); hX1 = silu_f(hX1);
        float cw = hA0 * cw2l0 + hA1 * cw2l1;
        float xw = hX0 * xw2l0 + hX1 * xw2l1;
        #pragma unroll
        for (int off = 16; off > 0; off >>= 1) {
            cw += __shfl_xor_sync(0xffffffffu, cw, off);
            xw += __shfl_xor_sync(0xffffffffu, xw, off);
        }
        cw += cb2r; xw += xb2r;

        int j = jn[e];
        float cj0 = cb3[3 * j], cj1 = cb3[3 * j + 1], cj2 = cb3[3 * j + 2];
        float bj0 = cmb[3 * j], bj1 = cmb[3 * j + 1], bj2 = cmb[3 * j + 2];
        float rr, xx;
        if (lane == 0)      { rr = ci0 - cj0; xx = ai1 * bj2 - ai2 * bj1; }
        else if (lane == 1) { rr = ci1 - cj1; xx = ai2 * bj0 - ai0 * bj2; }
        else                { rr = ci2 - cj2; xx = ai0 * bj1 - ai1 * bj0; }
        if (lane < 3) caccl = fmaf(cw, rr, fmaf(xw, xx, caccl));
    }
    if (lane < 3) atomicAdd(&s_cacc[lane], caccl);
    __syncthreads();

    // m_i = sum over warps
    if (tid < 16) {
        float acc = 0.f;
        #pragma unroll
        for (int w = 0; w < 8; w++) acc += s_maccw[w * 16 + tid];
        s_macc[tid] = acc;
    }
    __syncthreads();

    // node MLP: hidden = silu(NH + m_i @ node_w1[128:144] + b1)
    {
        float hv = g_NH[(size_t)bi * 256 + tid] + nb1[tid];
        #pragma unroll
        for (int c = 0; c < 16; c++) hv = fmaf(s_macc[c], nw1[(128 + c) * 256 + tid], hv);
        s_hid[tid] = silu_f(hv);
    }
    __syncthreads();
    // out = hidden @ node_w2 + b2 + feats (split-K across thread halves)
    {
        int half = tid >> 7, dcol = tid & 127;
        const float* w2 = nw2 + half * 128 * 128 + dcol;
        const float* hh = s_hid + half * 128;
        float acc = 0.f;
        #pragma unroll 8
        for (int qq = 0; qq < 128; qq++) acc = fmaf(hh[qq], w2[qq * 128], acc);
        if (half == 0) s_out0[dcol] = acc; else s_out1[dcol] = acc;
    }
    __syncthreads();
    if (tid < 128) {
        out[(size_t)bi * 128 + tid] =
            s_out0[tid] + s_out1[tid] + nb2[tid] + feats[(size_t)bi * 128 + tid];
    }
    if (tid < 3) {
        float* outc = out + (size_t)NBI * DD;
        outc[(size_t)bi * 3 + tid] = coors[(size_t)bi * 3 + tid] + s_cacc[tid];
    }
}

#define SMEM_BYTES (17964 * 4)

extern "C" void kernel_launch(void* const* d_in, const int* in_sizes, int n_in,
                              void* d_out, int out_size) {
    const float* feats = (const float*)d_in[0];
    const float* coors = (const float*)d_in[1];
    const float* ew1   = (const float*)d_in[2];
    const float* eb1   = (const float*)d_in[3];
    const float* ew2   = (const float*)d_in[4];
    const float* eb2   = (const float*)d_in[5];
    const float* cw1   = (const float*)d_in[6];
    const float* cb1   = (const float*)d_in[7];
    const float* cw2   = (const float*)d_in[8];
    const float* cb2   = (const float*)d_in[9];
    const float* xw1   = (const float*)d_in[10];
    const float* xb1   = (const float*)d_in[11];
    const float* xw2   = (const float*)d_in[12];
    const float* xb2   = (const float*)d_in[13];
    const float* nw1   = (const float*)d_in[14];
    const float* nb1   = (const float*)d_in[15];
    const float* nw2   = (const float*)d_in[16];
    const float* nb2   = (const float*)d_in[17];
    float* out = (float*)d_out;

    cudaFuncSetAttribute(k_main, cudaFuncAttributeMaxDynamicSharedMemorySize, SMEM_BYTES);

    k_mean<<<NB, 256>>>(coors);
    k_precompAB<<<NBI / 64, 256>>>(feats, ew1);
    k_precompNH<<<NBI / 64, 256>>>(feats, nw1);
    k_topk<<<NBI, 256>>>(coors);
    k_main<<<NBI, 256, SMEM_BYTES>>>(feats, coors, ew1, eb1, ew2, eb2,
                                     cw1, cb1, cw2, cb2, xw1, xb1, xw2, xb2,
                                     nw1, nb1, nw2, nb2, out);
}

// round 5
// speedup vs baseline: 2.0439x; 2.0439x over previous
#include <cuda_runtime.h>
#include <math.h>

#define NB 4
#define NN 2048
#define DD 128
#define KK 32
#define H1 530      // 2*EIN
#define H1P 544     // padded to 17*32
#define NBI (NB*NN) // 8192

// ---------------- scratch (static device globals; no allocation) ----------------
__device__ float g_A  [NBI * H1];        // feats_i @ W1[0:128]
__device__ float g_Bv [NBI * H1P + 64];  // feats_j @ W1[128:256], padded stride+tail
__device__ float g_NH [NBI * 256];       // feats   @ node_w1[0:128]
__device__ float g_cm [NBI * 3];         // mean-centered coords
__device__ int   g_nbidx[NBI * KK];
__device__ float g_dk   [NBI * KK];

// ---------------- fast SiLU: FMA-pipe Taylor sigmoid, MUFU fallback -------------
__device__ __forceinline__ float silu_f(float x) {
    float ax = fabsf(x);
    if (ax < 1.0f) {
        float x2 = x * x;
        float s = 31.0f / 1451520.0f;
        s = fmaf(s, x2, -17.0f / 80640.0f);
        s = fmaf(s, x2,  1.0f / 480.0f);
        s = fmaf(s, x2, -1.0f / 48.0f);
        s = fmaf(s, x2,  0.25f);
        return x * fmaf(x, s, 0.5f);
    }
    return x / (1.0f + __expf(-x));
}

// ---------------- mean-center coords ----------------
__global__ void __launch_bounds__(256) k_mean(const float* __restrict__ coors) {
    int b = blockIdx.x, t = threadIdx.x;
    __shared__ float rx[256], ry[256], rz[256];
    const float* cb = coors + (size_t)b * NN * 3;
    float sx = 0.f, sy = 0.f, sz = 0.f;
    for (int j = t; j < NN; j += 256) {
        sx += cb[3 * j]; sy += cb[3 * j + 1]; sz += cb[3 * j + 2];
    }
    rx[t] = sx; ry[t] = sy; rz[t] = sz;
    __syncthreads();
    for (int s = 128; s > 0; s >>= 1) {
        if (t < s) { rx[t] += rx[t + s]; ry[t] += ry[t + s]; rz[t] += rz[t + s]; }
        __syncthreads();
    }
    float mx = rx[0] * (1.0f / NN), my = ry[0] * (1.0f / NN), mz = rz[0] * (1.0f / NN);
    float* cmb = g_cm + (size_t)b * NN * 3;
    for (int j = t; j < NN; j += 256) {
        cmb[3 * j]     = cb[3 * j]     - mx;
        cmb[3 * j + 1] = cb[3 * j + 1] - my;
        cmb[3 * j + 2] = cb[3 * j + 2] - mz;
    }
}

// ---------------- precompute A = F@W1a, Bv = F@W1b (8 nodes / warp) --------------
__global__ void __launch_bounds__(256) k_precompAB(const float* __restrict__ feats,
                                                   const float* __restrict__ ew1) {
    int n0 = blockIdx.x * 64;
    __shared__ float sf[64 * 128];
    int t = threadIdx.x;
    #pragma unroll 4
    for (int idx = t; idx < 64 * 128; idx += 256) sf[idx] = feats[(size_t)n0 * 128 + idx];
    __syncthreads();
    int ng = t >> 5, lane = t & 31;
    const float2* fq[8];
    #pragma unroll
    for (int q = 0; q < 8; q++) fq[q] = (const float2*)(sf + (ng * 8 + q) * 128);
    for (int cc = 0; cc < H1; cc += 32) {
        int c = cc + lane;
        int cs = (c < H1) ? c : (H1 - 1);
        float a[8], bb[8];
        #pragma unroll
        for (int q = 0; q < 8; q++) { a[q] = 0.f; bb[q] = 0.f; }
        #pragma unroll 2
        for (int dd = 0; dd < 64; dd++) {
            float wA0 = ew1[(size_t)(2 * dd) * H1 + cs];
            float wA1 = ew1[(size_t)(2 * dd + 1) * H1 + cs];
            float wB0 = ew1[(size_t)(128 + 2 * dd) * H1 + cs];
            float wB1 = ew1[(size_t)(129 + 2 * dd) * H1 + cs];
            #pragma unroll
            for (int q = 0; q < 8; q++) {
                float2 fv = fq[q][dd];
                a[q]  = fmaf(fv.x, wA0, a[q]);  a[q]  = fmaf(fv.y, wA1, a[q]);
                bb[q] = fmaf(fv.x, wB0, bb[q]); bb[q] = fmaf(fv.y, wB1, bb[q]);
            }
        }
        if (c < H1) {
            #pragma unroll
            for (int q = 0; q < 8; q++) {
                int node = n0 + ng * 8 + q;
                g_A [(size_t)node * H1  + c] = a[q];
                g_Bv[(size_t)node * H1P + c] = bb[q];
            }
        }
    }
}

// ---------------- precompute NH = F @ node_w1[0:128] ----------------------------
__global__ void __launch_bounds__(256) k_precompNH(const float* __restrict__ feats,
                                                   const float* __restrict__ nw1) {
    int n0 = blockIdx.x * 64;
    __shared__ float sf[64 * 128];
    int t = threadIdx.x;
    #pragma unroll 4
    for (int idx = t; idx < 64 * 128; idx += 256) sf[idx] = feats[(size_t)n0 * 128 + idx];
    __syncthreads();
    int ng = t >> 5, lane = t & 31;
    const float2* fq[8];
    #pragma unroll
    for (int q = 0; q < 8; q++) fq[q] = (const float2*)(sf + (ng * 8 + q) * 128);
    for (int cc = 0; cc < 256; cc += 32) {
        int c = cc + lane;
        float a[8];
        #pragma unroll
        for (int q = 0; q < 8; q++) a[q] = 0.f;
        #pragma unroll 2
        for (int dd = 0; dd < 64; dd++) {
            float w0 = nw1[(size_t)(2 * dd) * 256 + c];
            float w1 = nw1[(size_t)(2 * dd + 1) * 256 + c];
            #pragma unroll
            for (int q = 0; q < 8; q++) {
                float2 fv = fq[q][dd];
                a[q] = fmaf(fv.x, w0, a[q]); a[q] = fmaf(fv.y, w1, a[q]);
            }
        }
        #pragma unroll
        for (int q = 0; q < 8; q++)
            g_NH[(size_t)(n0 + ng * 8 + q) * 256 + c] = a[q];
    }
}

// ---------------- top-K: binary search on float bit-keys in registers ------------
__global__ void __launch_bounds__(256) k_topk(const float* __restrict__ coors) {
    int bi = blockIdx.x;
    int b  = bi >> 11;
    int t = threadIdx.x, lane = t & 31, wid = t >> 5;
    __shared__ int s_cnt[8];
    __shared__ unsigned s_loS, s_hiS, s_thr;
    __shared__ int s_done, s_sel, s_curmin;

    const float* cb = coors + (size_t)b * NN * 3;
    float cx = coors[(size_t)bi * 3], cy = coors[(size_t)bi * 3 + 1], cz = coors[(size_t)bi * 3 + 2];
    float d[8]; unsigned ud[8];
    #pragma unroll
    for (int i = 0; i < 8; i++) {
        int j = t + i * 256;
        float dx = cx - cb[3 * j], dy = cy - cb[3 * j + 1], dz = cz - cb[3 * j + 2];
        float dv = dx * dx + dy * dy + dz * dz;
        d[i] = dv; ud[i] = __float_as_uint(dv);
    }
    if (t == 0) { s_loS = 0u; s_hiS = 0x7f800000u; s_done = 0; s_sel = 0; s_curmin = -1; }
    __syncthreads();

    #pragma unroll 1
    for (int it = 0; it < 34; it++) {
        unsigned lo = s_loS, hi = s_hiS;
        unsigned mid = lo + ((hi - lo) >> 1);
        int c = 0;
        #pragma unroll
        for (int i = 0; i < 8; i++) c += (ud[i] <= mid) ? 1 : 0;
        #pragma unroll
        for (int off = 16; off; off >>= 1) c += __shfl_xor_sync(0xffffffffu, c, off);
        if (lane == 0) s_cnt[wid] = c;
        __syncthreads();
        if (t == 0) {
            int tot = 0;
            #pragma unroll
            for (int w = 0; w < 8; w++) tot += s_cnt[w];
            if (tot == KK) { s_thr = mid; s_done = 1; }
            else {
                unsigned nlo = lo, nhi = hi;
                if (tot > KK) nhi = mid; else nlo = mid + 1;
                if (nlo >= nhi) { s_thr = nlo; s_done = 2; }
                s_loS = nlo; s_hiS = nhi;
            }
        }
        __syncthreads();
        if (s_done) break;
    }
    unsigned thr = s_thr; int mode = s_done;

    #pragma unroll
    for (int i = 0; i < 8; i++) {
        bool sel = (mode == 1) ? (ud[i] <= thr) : (ud[i] < thr);
        if (sel) {
            int p = atomicAdd(&s_sel, 1);
            g_nbidx[(size_t)bi * KK + p] = t + i * 256;
            g_dk   [(size_t)bi * KK + p] = d[i];
        }
    }
    __syncthreads();
    if (mode == 2) {
        int C = s_sel;
        for (int k = C; k < KK; k++) {
            int prev = s_curmin;
            int cand = 0x7fffffff;
            #pragma unroll
            for (int i = 0; i < 8; i++) {
                int j = t + i * 256;
                if (ud[i] == thr && j > prev && j < cand) cand = j;
            }
            #pragma unroll
            for (int off = 16; off; off >>= 1) {
                int o = __shfl_xor_sync(0xffffffffu, cand, off);
                cand = min(cand, o);
            }
            if (lane == 0) s_cnt[wid] = cand;
            __syncthreads();
            if (t == 0) {
                int mn = s_cnt[0];
                #pragma unroll
                for (int w = 1; w < 8; w++) mn = min(mn, s_cnt[w]);
                g_nbidx[(size_t)bi * KK + k] = mn;
                g_dk   [(size_t)bi * KK + k] = __uint_as_float(thr);
                s_curmin = mn;
            }
            __syncthreads();
        }
    }
}

// ---------------- reduce-scatter step over 2*HALF partials ----------------------
template <int MASK, int HALF>
__device__ __forceinline__ void rstep(float* pr, int lane) {
    bool hi = (lane & MASK) != 0;
    #pragma unroll
    for (int i = 0; i < HALF; i++) {
        float sent = hi ? pr[i] : pr[HALF + i];
        float recv = __shfl_xor_sync(0xffffffffu, sent, MASK);
        pr[i] = (hi ? pr[HALF + i] : pr[i]) + recv;
    }
}

// ---------------- fused edge MLP + coord update + node MLP ----------------------
__global__ void __launch_bounds__(256, 2) k_main(
    const float* __restrict__ feats, const float* __restrict__ coors,
    const float* __restrict__ ew1,  const float* __restrict__ eb1,
    const float* __restrict__ ew2,  const float* __restrict__ eb2,
    const float* __restrict__ cw1g, const float* __restrict__ cb1g,
    const float* __restrict__ cw2g, const float* __restrict__ cb2g,
    const float* __restrict__ xw1g, const float* __restrict__ xb1g,
    const float* __restrict__ xw2g, const float* __restrict__ xb2g,
    const float* __restrict__ nw1,  const float* __restrict__ nb1,
    const float* __restrict__ nw2,  const float* __restrict__ nb2,
    float* __restrict__ out)
{
    extern __shared__ float smx[];
    float* s_base = smx;                     // 544
    float* s_w1c  = s_base + H1P;            // 9*544
    float* s_w2t  = s_w1c + 9 * H1P;         // 16*544
    float* s_cw1  = s_w2t + 16 * H1P;        // 1024
    float* s_xw1  = s_cw1 + 1024;            // 1024
    float* s_cb1  = s_xw1 + 1024;            // 64
    float* s_xb1  = s_cb1 + 64;              // 64
    float* s_cw2  = s_xb1 + 64;              // 64
    float* s_xw2  = s_cw2 + 64;              // 64
    float* s_b2   = s_xw2 + 64;              // 16
    float* s_enc  = s_b2 + 16;               // 288
    float* s_m    = s_enc + 288;             // 8 warps * 32
    float* s_maccw= s_m + 256;               // 8*16
    float* s_macc = s_maccw + 128;           // 16
    float* s_cacc = s_macc + 16;             // 4
    float* s_geo  = s_cacc + 4;              // 8
    float* s_hid  = s_geo + 8;               // 256
    float* s_out0 = s_hid + 256;             // 128
    float* s_out1 = s_out0 + 128;            // 128
    int*   s_nb   = (int*)(s_out1 + 128);    // 32

    int tid = threadIdx.x;
    int bi  = blockIdx.x;
    int b   = bi >> 11;

    for (int c = tid; c < H1P; c += 256)
        s_base[c] = (c < H1) ? (g_A[(size_t)bi * H1 + c] + eb1[c]) : 0.f;
    for (int idx = tid; idx < 9 * H1P; idx += 256) {
        int r = idx / H1P, c = idx - r * H1P;
        s_w1c[idx] = (c < H1) ? ew1[(256 + r) * H1 + c] : 0.f;
    }
    for (int idx = tid; idx < 16 * H1P; idx += 256) {
        int c = idx / H1P, el = idx - c * H1P;
        s_w2t[idx] = (el < H1) ? ew2[el * 16 + c] : 0.f;
    }
    for (int idx = tid; idx < 1024; idx += 256) { s_cw1[idx] = cw1g[idx]; s_xw1[idx] = xw1g[idx]; }
    if (tid < 64) { s_cb1[tid] = cb1g[tid]; s_xb1[tid] = xb1g[tid]; s_cw2[tid] = cw2g[tid]; s_xw2[tid] = xw2g[tid]; }
    if (tid < 16) s_b2[tid] = eb2[tid];
    if (tid < 4)  s_cacc[tid] = 0.f;
    if (tid < 32) {
        float dv = g_dk[(size_t)bi * KK + tid];
        s_enc[tid * 9 + 0] = sinf(dv);
        s_enc[tid * 9 + 1] = sinf(0.5f * dv);
        s_enc[tid * 9 + 2] = sinf(0.25f * dv);
        s_enc[tid * 9 + 3] = sinf(0.125f * dv);
        s_enc[tid * 9 + 4] = cosf(dv);
        s_enc[tid * 9 + 5] = cosf(0.5f * dv);
        s_enc[tid * 9 + 6] = cosf(0.25f * dv);
        s_enc[tid * 9 + 7] = cosf(0.125f * dv);
        s_enc[tid * 9 + 8] = dv;
        s_nb[tid] = g_nbidx[(size_t)bi * KK + tid];
    }
    if (tid < 3) { s_geo[tid] = coors[(size_t)bi * 3 + tid]; s_geo[3 + tid] = g_cm[(size_t)bi * 3 + tid]; }
    __syncthreads();

    int lane = tid & 31, wid = tid >> 5;
    float cb2r = cb2g[0], xb2r = xb2g[0];
    float ci0 = s_geo[0], ci1 = s_geo[1], ci2 = s_geo[2];
    float ai0 = s_geo[3], ai1 = s_geo[4], ai2 = s_geo[5];
    const float* cb3 = coors + (size_t)b * NN * 3;
    const float* cmb = g_cm  + (size_t)b * NN * 3;

    float caccl = 0.f;
    float maccr = 0.f;   // per-lane (lane<16) running m_i partial for this warp

    // two passes; each pass: this warp handles edges (pass*16 + wid*2 + {0,1})
    #pragma unroll 1
    for (int pass = 0; pass < 2; pass++) {
        int e0 = pass * 16 + wid * 2;
        int j0 = s_nb[e0], j1 = s_nb[e0 + 1];
        const float* bv0 = g_Bv + ((size_t)b * NN + j0) * H1P;
        const float* bv1 = g_Bv + ((size_t)b * NN + j1) * H1P;
        float e9a[9], e9b[9];
        #pragma unroll
        for (int r = 0; r < 9; r++) {
            e9a[r] = s_enc[e0 * 9 + r];
            e9b[r] = s_enc[(e0 + 1) * 9 + r];
        }
        float pr[32];
        #pragma unroll
        for (int i = 0; i < 32; i++) pr[i] = 0.f;

        float bvc0 = bv0[lane], bvc1 = bv1[lane];
        #pragma unroll 1
        for (int tt = 0; tt < 17; tt++) {
            int el = tt * 32 + lane;
            float bvn0 = bv0[el + 32];   // tail pad covers tt=16 overrun
            float bvn1 = bv1[el + 32];
            float base = s_base[el];
            float w1r[9];
            #pragma unroll
            for (int r = 0; r < 9; r++) w1r[r] = s_w1c[r * H1P + el];
            float acc0 = base + bvc0, acc1 = base + bvc1;
            #pragma unroll
            for (int r = 0; r < 9; r++) {
                acc0 = fmaf(e9a[r], w1r[r], acc0);
                acc1 = fmaf(e9b[r], w1r[r], acc1);
            }
            float h0 = silu_f(acc0), h1 = silu_f(acc1);
            #pragma unroll
            for (int c = 0; c < 16; c++) {
                float w2 = s_w2t[c * H1P + el];
                pr[c]      = fmaf(h0, w2, pr[c]);
                pr[16 + c] = fmaf(h1, w2, pr[16 + c]);
            }
            bvc0 = bvn0; bvc1 = bvn1;
        }

        // reduce-scatter: lane ends owning id=lane (local edge = lane>>4, c = lane&15)
        rstep<16, 16>(pr, lane);
        rstep<8, 8>(pr, lane);
        rstep<4, 4>(pr, lane);
        rstep<2, 2>(pr, lane);
        rstep<1, 1>(pr, lane);

        float mv = silu_f(pr[0] + s_b2[lane & 15]);
        s_m[wid * 32 + lane] = mv;
        __syncwarp();
        if (lane < 16) maccr += s_m[wid * 32 + lane] + s_m[wid * 32 + 16 + lane];

        // coor MLPs + geometry for the 2 edges
        #pragma unroll 1
        for (int e = 0; e < 2; e++) {
            const float* mm = s_m + wid * 32 + e * 16;
            float hA0 = s_cb1[lane], hA1 = s_cb1[lane + 32];
            float hX0 = s_xb1[lane], hX1 = s_xb1[lane + 32];
            #pragma unroll
            for (int c = 0; c < 16; c++) {
                float m = mm[c];
                hA0 = fmaf(m, s_cw1[c * 64 + lane],      hA0);
                hA1 = fmaf(m, s_cw1[c * 64 + lane + 32], hA1);
                hX0 = fmaf(m, s_xw1[c * 64 + lane],      hX0);
                hX1 = fmaf(m, s_xw1[c * 64 + lane + 32], hX1);
            }
            hA0 = silu_f(hA0); hA1 = silu_f(hA1); hX0 = silu_f(hX0); hX1 = silu_f(hX1);
            float cw = hA0 * s_cw2[lane] + hA1 * s_cw2[lane + 32];
            float xw = hX0 * s_xw2[lane] + hX1 * s_xw2[lane + 32];
            #pragma unroll
            for (int off = 16; off > 0; off >>= 1) {
                cw += __shfl_xor_sync(0xffffffffu, cw, off);
                xw += __shfl_xor_sync(0xffffffffu, xw, off);
            }
            cw += cb2r; xw += xb2r;

            int j = (e == 0) ? j0 : j1;
            float cj0 = cb3[3 * j], cj1 = cb3[3 * j + 1], cj2 = cb3[3 * j + 2];
            float bj0 = cmb[3 * j], bj1 = cmb[3 * j + 1], bj2 = cmb[3 * j + 2];
            float rr, xx;
            if (lane == 0)      { rr = ci0 - cj0; xx = ai1 * bj2 - ai2 * bj1; }
            else if (lane == 1) { rr = ci1 - cj1; xx = ai2 * bj0 - ai0 * bj2; }
            else                { rr = ci2 - cj2; xx = ai0 * bj1 - ai1 * bj0; }
            if (lane < 3) caccl = fmaf(cw, rr, fmaf(xw, xx, caccl));
        }
    }
    if (lane < 16) s_maccw[wid * 16 + lane] = maccr;
    if (lane < 3) atomicAdd(&s_cacc[lane], caccl);
    __syncthreads();

    // m_i = sum over warps
    if (tid < 16) {
        float acc = 0.f;
        #pragma unroll
        for (int w = 0; w < 8; w++) acc += s_maccw[w * 16 + tid];
        s_macc[tid] = acc;
    }
    __syncthreads();

    // node MLP: hidden = silu(NH + m_i @ node_w1[128:144] + b1)
    {
        float hv = g_NH[(size_t)bi * 256 + tid] + nb1[tid];
        #pragma unroll
        for (int c = 0; c < 16; c++) hv = fmaf(s_macc[c], nw1[(128 + c) * 256 + tid], hv);
        s_hid[tid] = silu_f(hv);
    }
    __syncthreads();
    // out = hidden @ node_w2 + b2 + feats (split-K across thread halves)
    {
        int half = tid >> 7, dcol = tid & 127;
        const float* w2 = nw2 + half * 128 * 128 + dcol;
        const float* hh = s_hid + half * 128;
        float acc = 0.f;
        #pragma unroll 8
        for (int qq = 0; qq < 128; qq++) acc = fmaf(hh[qq], w2[qq * 128], acc);
        if (half == 0) s_out0[dcol] = acc; else s_out1[dcol] = acc;
    }
    __syncthreads();
    if (tid < 128) {
        out[(size_t)bi * 128 + tid] =
            s_out0[tid] + s_out1[tid] + nb2[tid] + feats[(size_t)bi * 128 + tid];
    }
    if (tid < 3) {
        float* outc = out + (size_t)NBI * DD;
        outc[(size_t)bi * 3 + tid] = coors[(size_t)bi * 3 + tid] + s_cacc[tid];
    }
}

#define SMEM_BYTES (17708 * 4)

extern "C" void kernel_launch(void* const* d_in, const int* in_sizes, int n_in,
                              void* d_out, int out_size) {
    const float* feats = (const float*)d_in[0];
    const float* coors = (const float*)d_in[1];
    const float* ew1   = (const float*)d_in[2];
    const float* eb1   = (const float*)d_in[3];
    const float* ew2   = (const float*)d_in[4];
    const float* eb2   = (const float*)d_in[5];
    const float* cw1   = (const float*)d_in[6];
    const float* cb1   = (const float*)d_in[7];
    const float* cw2   = (const float*)d_in[8];
    const float* cb2   = (const float*)d_in[9];
    const float* xw1   = (const float*)d_in[10];
    const float* xb1   = (const float*)d_in[11];
    const float* xw2   = (const float*)d_in[12];
    const float* xb2   = (const float*)d_in[13];
    const float* nw1   = (const float*)d_in[14];
    const float* nb1   = (const float*)d_in[15];
    const float* nw2   = (const float*)d_in[16];
    const float* nb2   = (const float*)d_in[17];
    float* out = (float*)d_out;

    cudaFuncSetAttribute(k_main, cudaFuncAttributeMaxDynamicSharedMemorySize, SMEM_BYTES);

    k_mean<<<NB, 256>>>(coors);
    k_precompAB<<<NBI / 64, 256>>>(feats, ew1);
    k_precompNH<<<NBI / 64, 256>>>(feats, nw1);
    k_topk<<<NBI, 256>>>(coors);
    k_main<<<NBI, 256, SMEM_BYTES>>>(feats, coors, ew1, eb1, ew2, eb2,
                                     cw1, cb1, cw2, cb2, xw1, xb1, xw2, xb2,
                                     nw1, nb1, nw2, nb2, out);
}

// round 6
// speedup vs baseline: 2.4644x; 1.2057x over previous
#include <cuda_runtime.h>
#include <math.h>

#define NB 4
#define NN 2048
#define DD 128
#define KK 32
#define H1 530      // 2*EIN
#define H1P 544     // padded to 17*32
#define NBI (NB*NN) // 8192

typedef unsigned long long ull;
typedef unsigned int uint;

// ---------------- scratch (static device globals; no allocation) ----------------
__device__ float g_A  [NBI * H1];        // feats_i @ W1[0:128]
__device__ float g_Bv [NBI * H1P + 64];  // feats_j @ W1[128:256], padded stride+tail
__device__ float g_NH [NBI * 256];       // feats   @ node_w1[0:128]
__device__ float g_cm [NBI * 3];         // mean-centered coords
__device__ int   g_nbidx[NBI * KK];
__device__ float g_dk   [NBI * KK];

// ---------------- packed f32x2 primitives (Blackwell) ---------------------------
__device__ __forceinline__ ull pk2(float lo, float hi) {
    ull r; asm("mov.b64 %0,{%1,%2};" : "=l"(r) : "f"(lo), "f"(hi)); return r;
}
__device__ __forceinline__ void upk2(float& lo, float& hi, ull v) {
    asm("mov.b64 {%0,%1},%2;" : "=f"(lo), "=f"(hi) : "l"(v));
}
__device__ __forceinline__ ull fma2(ull a, ull b, ull c) {
    ull d; asm("fma.rn.f32x2 %0,%1,%2,%3;" : "=l"(d) : "l"(a), "l"(b), "l"(c)); return d;
}
__device__ __forceinline__ ull add2(ull a, ull b) {
    ull d; asm("add.rn.f32x2 %0,%1,%2;" : "=l"(d) : "l"(a), "l"(b)); return d;
}
__device__ __forceinline__ ull mul2(ull a, ull b) {
    ull d; asm("mul.rn.f32x2 %0,%1,%2;" : "=l"(d) : "l"(a), "l"(b)); return d;
}
__device__ __forceinline__ ull shflx64(ull v, int m) {
    uint lo, hi;
    asm("mov.b64 {%0,%1},%2;" : "=r"(lo), "=r"(hi) : "l"(v));
    lo = __shfl_xor_sync(0xffffffffu, lo, m);
    hi = __shfl_xor_sync(0xffffffffu, hi, m);
    ull r; asm("mov.b64 %0,{%1,%2};" : "=l"(r) : "r"(lo), "r"(hi)); return r;
}

// packed silu with exact scalar fallback for |x|>=1 (never taken in practice)
#define SILU2(res, xin) do { \
    ull _x = (xin); \
    ull _x2 = mul2(_x, _x); \
    ull _s = fma2(CP4, _x2, CP3); \
    _s = fma2(_s, _x2, CP2); \
    _s = fma2(_s, _x2, CP1); \
    _s = fma2(_s, _x2, CP0); \
    ull _t = fma2(_x, _s, CHALF); \
    (res) = mul2(_x, _t); \
    float _a, _b; upk2(_a, _b, _x); \
    if (fmaxf(fabsf(_a), fabsf(_b)) >= 1.0f) { \
        float _r0 = _a / (1.0f + __expf(-_a)); \
        float _r1 = _b / (1.0f + __expf(-_b)); \
        (res) = pk2(_r0, _r1); \
    } \
} while (0)

// ---------------- scalar fast SiLU (node / coor phases) -------------------------
__device__ __forceinline__ float silu_f(float x) {
    float ax = fabsf(x);
    if (ax < 1.0f) {
        float x2 = x * x;
        float s = 31.0f / 1451520.0f;
        s = fmaf(s, x2, -17.0f / 80640.0f);
        s = fmaf(s, x2,  1.0f / 480.0f);
        s = fmaf(s, x2, -1.0f / 48.0f);
        s = fmaf(s, x2,  0.25f);
        return x * fmaf(x, s, 0.5f);
    }
    return x / (1.0f + __expf(-x));
}

// ---------------- merged precompute: A, Bv, NH (8 nodes / warp) ------------------
__global__ void __launch_bounds__(256) k_precomp(const float* __restrict__ feats,
                                                 const float* __restrict__ ew1,
                                                 const float* __restrict__ nw1) {
    int n0 = blockIdx.x * 64;
    __shared__ float sf[64 * 128];
    int t = threadIdx.x;
    #pragma unroll 4
    for (int idx = t; idx < 64 * 128; idx += 256) sf[idx] = feats[(size_t)n0 * 128 + idx];
    __syncthreads();
    int ng = t >> 5, lane = t & 31;
    const float2* fq[8];
    #pragma unroll
    for (int q = 0; q < 8; q++) fq[q] = (const float2*)(sf + (ng * 8 + q) * 128);

    // A / Bv
    for (int cc = 0; cc < H1; cc += 32) {
        int c = cc + lane;
        int cs = (c < H1) ? c : (H1 - 1);
        float a[8], bb[8];
        #pragma unroll
        for (int q = 0; q < 8; q++) { a[q] = 0.f; bb[q] = 0.f; }
        #pragma unroll 2
        for (int dd = 0; dd < 64; dd++) {
            float wA0 = ew1[(size_t)(2 * dd) * H1 + cs];
            float wA1 = ew1[(size_t)(2 * dd + 1) * H1 + cs];
            float wB0 = ew1[(size_t)(128 + 2 * dd) * H1 + cs];
            float wB1 = ew1[(size_t)(129 + 2 * dd) * H1 + cs];
            #pragma unroll
            for (int q = 0; q < 8; q++) {
                float2 fv = fq[q][dd];
                a[q]  = fmaf(fv.x, wA0, a[q]);  a[q]  = fmaf(fv.y, wA1, a[q]);
                bb[q] = fmaf(fv.x, wB0, bb[q]); bb[q] = fmaf(fv.y, wB1, bb[q]);
            }
        }
        if (c < H1) {
            #pragma unroll
            for (int q = 0; q < 8; q++) {
                int node = n0 + ng * 8 + q;
                g_A [(size_t)node * H1  + c] = a[q];
                g_Bv[(size_t)node * H1P + c] = bb[q];
            }
        }
    }

    // NH
    for (int cc = 0; cc < 256; cc += 32) {
        int c = cc + lane;
        float a[8];
        #pragma unroll
        for (int q = 0; q < 8; q++) a[q] = 0.f;
        #pragma unroll 2
        for (int dd = 0; dd < 64; dd++) {
            float w0 = nw1[(size_t)(2 * dd) * 256 + c];
            float w1 = nw1[(size_t)(2 * dd + 1) * 256 + c];
            #pragma unroll
            for (int q = 0; q < 8; q++) {
                float2 fv = fq[q][dd];
                a[q] = fmaf(fv.x, w0, a[q]); a[q] = fmaf(fv.y, w1, a[q]);
            }
        }
        #pragma unroll
        for (int q = 0; q < 8; q++)
            g_NH[(size_t)(n0 + ng * 8 + q) * 256 + c] = a[q];
    }
}

// ---------------- mean-center coords ----------------
__global__ void __launch_bounds__(256) k_mean(const float* __restrict__ coors) {
    int b = blockIdx.x, t = threadIdx.x;
    __shared__ float rx[256], ry[256], rz[256];
    const float* cb = coors + (size_t)b * NN * 3;
    float sx = 0.f, sy = 0.f, sz = 0.f;
    for (int j = t; j < NN; j += 256) {
        sx += cb[3 * j]; sy += cb[3 * j + 1]; sz += cb[3 * j + 2];
    }
    rx[t] = sx; ry[t] = sy; rz[t] = sz;
    __syncthreads();
    for (int s = 128; s > 0; s >>= 1) {
        if (t < s) { rx[t] += rx[t + s]; ry[t] += ry[t + s]; rz[t] += rz[t + s]; }
        __syncthreads();
    }
    float mx = rx[0] * (1.0f / NN), my = ry[0] * (1.0f / NN), mz = rz[0] * (1.0f / NN);
    float* cmb = g_cm + (size_t)b * NN * 3;
    for (int j = t; j < NN; j += 256) {
        cmb[3 * j]     = cb[3 * j]     - mx;
        cmb[3 * j + 1] = cb[3 * j + 1] - my;
        cmb[3 * j + 2] = cb[3 * j + 2] - mz;
    }
}

// ---------------- top-K: binary search on float bit-keys in registers ------------
__global__ void __launch_bounds__(256) k_topk(const float* __restrict__ coors) {
    int bi = blockIdx.x;
    int b  = bi >> 11;
    int t = threadIdx.x, lane = t & 31, wid = t >> 5;
    __shared__ int s_cnt[8];
    __shared__ unsigned s_loS, s_hiS, s_thr;
    __shared__ int s_done, s_sel, s_curmin;

    const float* cb = coors + (size_t)b * NN * 3;
    float cx = coors[(size_t)bi * 3], cy = coors[(size_t)bi * 3 + 1], cz = coors[(size_t)bi * 3 + 2];
    float d[8]; unsigned ud[8];
    #pragma unroll
    for (int i = 0; i < 8; i++) {
        int j = t + i * 256;
        float dx = cx - cb[3 * j], dy = cy - cb[3 * j + 1], dz = cz - cb[3 * j + 2];
        float dv = dx * dx + dy * dy + dz * dz;
        d[i] = dv; ud[i] = __float_as_uint(dv);
    }
    if (t == 0) { s_loS = 0u; s_hiS = 0x7f800000u; s_done = 0; s_sel = 0; s_curmin = -1; }
    __syncthreads();

    #pragma unroll 1
    for (int it = 0; it < 34; it++) {
        unsigned lo = s_loS, hi = s_hiS;
        unsigned mid = lo + ((hi - lo) >> 1);
        int c = 0;
        #pragma unroll
        for (int i = 0; i < 8; i++) c += (ud[i] <= mid) ? 1 : 0;
        #pragma unroll
        for (int off = 16; off; off >>= 1) c += __shfl_xor_sync(0xffffffffu, c, off);
        if (lane == 0) s_cnt[wid] = c;
        __syncthreads();
        if (t == 0) {
            int tot = 0;
            #pragma unroll
            for (int w = 0; w < 8; w++) tot += s_cnt[w];
            if (tot == KK) { s_thr = mid; s_done = 1; }
            else {
                unsigned nlo = lo, nhi = hi;
                if (tot > KK) nhi = mid; else nlo = mid + 1;
                if (nlo >= nhi) { s_thr = nlo; s_done = 2; }
                s_loS = nlo; s_hiS = nhi;
            }
        }
        __syncthreads();
        if (s_done) break;
    }
    unsigned thr = s_thr; int mode = s_done;

    #pragma unroll
    for (int i = 0; i < 8; i++) {
        bool sel = (mode == 1) ? (ud[i] <= thr) : (ud[i] < thr);
        if (sel) {
            int p = atomicAdd(&s_sel, 1);
            g_nbidx[(size_t)bi * KK + p] = t + i * 256;
            g_dk   [(size_t)bi * KK + p] = d[i];
        }
    }
    __syncthreads();
    if (mode == 2) {
        int C = s_sel;
        for (int k = C; k < KK; k++) {
            int prev = s_curmin;
            int cand = 0x7fffffff;
            #pragma unroll
            for (int i = 0; i < 8; i++) {
                int j = t + i * 256;
                if (ud[i] == thr && j > prev && j < cand) cand = j;
            }
            #pragma unroll
            for (int off = 16; off; off >>= 1) {
                int o = __shfl_xor_sync(0xffffffffu, cand, off);
                cand = min(cand, o);
            }
            if (lane == 0) s_cnt[wid] = cand;
            __syncthreads();
            if (t == 0) {
                int mn = s_cnt[0];
                #pragma unroll
                for (int w = 1; w < 8; w++) mn = min(mn, s_cnt[w]);
                g_nbidx[(size_t)bi * KK + k] = mn;
                g_dk   [(size_t)bi * KK + k] = __uint_as_float(thr);
                s_curmin = mn;
            }
            __syncthreads();
        }
    }
}

// ---------------- 64-bit packed reduce-scatter step -----------------------------
template <int MASK, int HALF>
__device__ __forceinline__ void rstep64(ull* q, int lane) {
    bool hi = (lane & MASK) != 0;
    #pragma unroll
    for (int i = 0; i < HALF; i++) {
        ull sent = hi ? q[i] : q[HALF + i];
        ull recv = shflx64(sent, MASK);
        q[i] = add2(hi ? q[HALF + i] : q[i], recv);
    }
}

// ---------------- fused edge MLP + coord update + node MLP ----------------------
// smem float offsets
#define O_BASE 0
#define O_W1P  544              // 5*H1P float2 = 5440 floats
#define O_W2P  (O_W1P + 5440)   // 8*H1P float2 = 8704 floats
#define O_CW1  (O_W2P + 8704)
#define O_XW1  (O_CW1 + 1024)
#define O_CB1  (O_XW1 + 1024)
#define O_XB1  (O_CB1 + 64)
#define O_CW2  (O_XB1 + 64)
#define O_XW2  (O_CW2 + 64)
#define O_B2   (O_XW2 + 64)
#define O_ENC  (O_B2 + 16)
#define O_M    (O_ENC + 288)
#define O_MACW (O_M + 256)
#define O_MACC (O_MACW + 128)
#define O_CACC (O_MACC + 16)
#define O_GEO  (O_CACC + 4)
#define O_HID  (O_GEO + 8)
#define O_OUT0 (O_HID + 256)
#define O_OUT1 (O_OUT0 + 128)
#define O_NB   (O_OUT1 + 128)
#define SMEM_FLOATS (O_NB + 32)
#define SMEM_BYTES (SMEM_FLOATS * 4)

__global__ void __launch_bounds__(256, 2) k_main(
    const float* __restrict__ feats, const float* __restrict__ coors,
    const float* __restrict__ ew1,  const float* __restrict__ eb1,
    const float* __restrict__ ew2,  const float* __restrict__ eb2,
    const float* __restrict__ cw1g, const float* __restrict__ cb1g,
    const float* __restrict__ cw2g, const float* __restrict__ cb2g,
    const float* __restrict__ xw1g, const float* __restrict__ xb1g,
    const float* __restrict__ xw2g, const float* __restrict__ xb2g,
    const float* __restrict__ nw1,  const float* __restrict__ nb1,
    const float* __restrict__ nw2,  const float* __restrict__ nb2,
    float* __restrict__ out)
{
    extern __shared__ float smx[];
    float* s_base = smx + O_BASE;
    float* s_w1p  = smx + O_W1P;
    float* s_w2p  = smx + O_W2P;
    float* s_cw1  = smx + O_CW1;
    float* s_xw1  = smx + O_XW1;
    float* s_cb1  = smx + O_CB1;
    float* s_xb1  = smx + O_XB1;
    float* s_cw2  = smx + O_CW2;
    float* s_xw2  = smx + O_XW2;
    float* s_b2   = smx + O_B2;
    float* s_enc  = smx + O_ENC;
    float* s_m    = smx + O_M;
    float* s_maccw= smx + O_MACW;
    float* s_macc = smx + O_MACC;
    float* s_cacc = smx + O_CACC;
    float* s_geo  = smx + O_GEO;
    float* s_hid  = smx + O_HID;
    float* s_out0 = smx + O_OUT0;
    float* s_out1 = smx + O_OUT1;
    int*   s_nb   = (int*)(smx + O_NB);

    int tid = threadIdx.x;
    int bi  = blockIdx.x;
    int b   = bi >> 11;

    // ---- prologue ----
    for (int c = tid; c < H1P; c += 256)
        s_base[c] = (c < H1) ? (g_A[(size_t)bi * H1 + c] + eb1[c]) : 0.f;
    // W1 r-pairs: s_w1p[(rp*H1P+el)*2+half] = ew1[(256+2rp+half)*H1+el]
    for (int idx = tid; idx < 5440; idx += 256) {
        int rp = idx / 1088, rem = idx - rp * 1088;
        int el = rem >> 1, half = rem & 1;
        int r = 2 * rp + half;
        s_w1p[idx] = (el < H1 && r < 9) ? ew1[(size_t)(256 + r) * H1 + el] : 0.f;
    }
    // W2 c-pairs: s_w2p[(cp*H1P+el)*2+half] = ew2[el*16 + 2cp+half]
    for (int idx = tid; idx < 8704; idx += 256) {
        int cp = idx / 1088, rem = idx - cp * 1088;
        int el = rem >> 1, half = rem & 1;
        s_w2p[idx] = (el < H1) ? ew2[(size_t)el * 16 + 2 * cp + half] : 0.f;
    }
    for (int idx = tid; idx < 1024; idx += 256) { s_cw1[idx] = cw1g[idx]; s_xw1[idx] = xw1g[idx]; }
    if (tid < 64) { s_cb1[tid] = cb1g[tid]; s_xb1[tid] = xb1g[tid]; s_cw2[tid] = cw2g[tid]; s_xw2[tid] = xw2g[tid]; }
    if (tid < 16) s_b2[tid] = eb2[tid];
    if (tid < 4)  s_cacc[tid] = 0.f;
    if (tid < 32) {
        float dv = g_dk[(size_t)bi * KK + tid];
        s_enc[tid * 9 + 0] = sinf(dv);
        s_enc[tid * 9 + 1] = sinf(0.5f * dv);
        s_enc[tid * 9 + 2] = sinf(0.25f * dv);
        s_enc[tid * 9 + 3] = sinf(0.125f * dv);
        s_enc[tid * 9 + 4] = cosf(dv);
        s_enc[tid * 9 + 5] = cosf(0.5f * dv);
        s_enc[tid * 9 + 6] = cosf(0.25f * dv);
        s_enc[tid * 9 + 7] = cosf(0.125f * dv);
        s_enc[tid * 9 + 8] = dv;
        s_nb[tid] = g_nbidx[(size_t)bi * KK + tid];
    }
    if (tid < 3) { s_geo[tid] = coors[(size_t)bi * 3 + tid]; s_geo[3 + tid] = g_cm[(size_t)bi * 3 + tid]; }
    __syncthreads();

    int lane = tid & 31, wid = tid >> 5;
    float cb2r = cb2g[0], xb2r = xb2g[0];
    float ci0 = s_geo[0], ci1 = s_geo[1], ci2 = s_geo[2];
    float ai0 = s_geo[3], ai1 = s_geo[4], ai2 = s_geo[5];
    const float* cb3 = coors + (size_t)b * NN * 3;
    const float* cmb = g_cm  + (size_t)b * NN * 3;

    const ull* w1p64 = (const ull*)s_w1p;
    const ull* w2p64 = (const ull*)s_w2p;
    const ull* b2_64 = (const ull*)s_b2;

    const ull CP4 = pk2(31.0f / 1451520.0f, 31.0f / 1451520.0f);
    const ull CP3 = pk2(-17.0f / 80640.0f, -17.0f / 80640.0f);
    const ull CP2 = pk2(1.0f / 480.0f, 1.0f / 480.0f);
    const ull CP1 = pk2(-1.0f / 48.0f, -1.0f / 48.0f);
    const ull CP0 = pk2(0.25f, 0.25f);
    const ull CHALF = pk2(0.5f, 0.5f);

    float caccl = 0.f;
    float maccr = 0.f;

    #pragma unroll 1
    for (int pass = 0; pass < 2; pass++) {
        int e0 = pass * 16 + wid * 2;
        int j0 = s_nb[e0], j1 = s_nb[e0 + 1];
        const float* bv0 = g_Bv + ((size_t)b * NN + j0) * H1P;
        const float* bv1 = g_Bv + ((size_t)b * NN + j1) * H1P;
        // packed r-pairs of enc for both edges
        ull e92a[5], e92b[5];
        #pragma unroll
        for (int rp = 0; rp < 5; rp++) {
            float a0 = s_enc[e0 * 9 + 2 * rp];
            float a1 = (2 * rp + 1 < 9) ? s_enc[e0 * 9 + 2 * rp + 1] : 0.f;
            float b0 = s_enc[(e0 + 1) * 9 + 2 * rp];
            float b1 = (2 * rp + 1 < 9) ? s_enc[(e0 + 1) * 9 + 2 * rp + 1] : 0.f;
            e92a[rp] = pk2(a0, a1);
            e92b[rp] = pk2(b0, b1);
        }

        ull q[16];   // q[0..7] = edge0 c-pairs, q[8..15] = edge1 c-pairs
        #pragma unroll
        for (int i = 0; i < 16; i++) q[i] = 0ULL;

        float bvc0 = bv0[lane], bvc1 = bv1[lane];
        #pragma unroll 1
        for (int tt = 0; tt < 17; tt++) {
            int el = tt * 32 + lane;
            float bvn0 = bv0[el + 32];    // tail pad covers tt=16 overrun
            float bvn1 = bv1[el + 32];
            float base = s_base[el];
            ull s0 = 0ULL, s1 = 0ULL;
            #pragma unroll
            for (int rp = 0; rp < 5; rp++) {
                ull w = w1p64[rp * H1P + el];
                s0 = fma2(e92a[rp], w, s0);
                s1 = fma2(e92b[rp], w, s1);
            }
            float p0, p1, r0, r1;
            upk2(p0, p1, s0);
            upk2(r0, r1, s1);
            float a0 = base + bvc0 + p0 + p1;
            float a1 = base + bvc1 + r0 + r1;
            ull h; SILU2(h, pk2(a0, a1));
            float h0, h1; upk2(h0, h1, h);
            ull h0d = pk2(h0, h0), h1d = pk2(h1, h1);
            #pragma unroll
            for (int cp = 0; cp < 8; cp++) {
                ull w = w2p64[cp * H1P + el];
                q[cp]     = fma2(h0d, w, q[cp]);
                q[8 + cp] = fma2(h1d, w, q[8 + cp]);
            }
            bvc0 = bvn0; bvc1 = bvn1;
        }

        // packed reduce-scatter: 16 ulls -> lane (lane>>1)&15 owns its pair fully
        rstep64<16, 8>(q, lane);
        rstep64<8, 4>(q, lane);
        rstep64<4, 2>(q, lane);
        rstep64<2, 1>(q, lane);
        q[0] = add2(q[0], shflx64(q[0], 1));

        {
            int idx = (lane >> 1) & 15;       // element id: e*8 + c2
            int e = idx >> 3, c2 = idx & 7;
            ull mb; SILU2(mb, add2(q[0], b2_64[c2]));
            if ((lane & 1) == 0) {
                ull* sm64 = (ull*)s_m;
                sm64[wid * 16 + e * 8 + c2] = mb;
            }
        }
        __syncwarp();
        if (lane < 16) maccr += s_m[wid * 32 + lane] + s_m[wid * 32 + 16 + lane];

        // coor MLPs + geometry for the 2 edges (scalar)
        #pragma unroll 1
        for (int e = 0; e < 2; e++) {
            const float* mm = s_m + wid * 32 + e * 16;
            float hA0 = s_cb1[lane], hA1 = s_cb1[lane + 32];
            float hX0 = s_xb1[lane], hX1 = s_xb1[lane + 32];
            #pragma unroll
            for (int c = 0; c < 16; c++) {
                float m = mm[c];
                hA0 = fmaf(m, s_cw1[c * 64 + lane],      hA0);
                hA1 = fmaf(m, s_cw1[c * 64 + lane + 32], hA1);
                hX0 = fmaf(m, s_xw1[c * 64 + lane],      hX0);
                hX1 = fmaf(m, s_xw1[c * 64 + lane + 32], hX1);
            }
            hA0 = silu_f(hA0); hA1 = silu_f(hA1); hX0 = silu_f(hX0); hX1 = silu_f(hX1);
            float cw = hA0 * s_cw2[lane] + hA1 * s_cw2[lane + 32];
            float xw = hX0 * s_xw2[lane] + hX1 * s_xw2[lane + 32];
            #pragma unroll
            for (int off = 16; off > 0; off >>= 1) {
                cw += __shfl_xor_sync(0xffffffffu, cw, off);
                xw += __shfl_xor_sync(0xffffffffu, xw, off);
            }
            cw += cb2r; xw += xb2r;

            int j = (e == 0) ? j0 : j1;
            float cj0 = cb3[3 * j], cj1 = cb3[3 * j + 1], cj2 = cb3[3 * j + 2];
            float bj0 = cmb[3 * j], bj1 = cmb[3 * j + 1], bj2 = cmb[3 * j + 2];
            float rr, xx;
            if (lane == 0)      { rr = ci0 - cj0; xx = ai1 * bj2 - ai2 * bj1; }
            else if (lane == 1) { rr = ci1 - cj1; xx = ai2 * bj0 - ai0 * bj2; }
            else                { rr = ci2 - cj2; xx = ai0 * bj1 - ai1 * bj0; }
            if (lane < 3) caccl = fmaf(cw, rr, fmaf(xw, xx, caccl));
        }
    }
    if (lane < 16) s_maccw[wid * 16 + lane] = maccr;
    if (lane < 3) atomicAdd(&s_cacc[lane], caccl);
    __syncthreads();

    if (tid < 16) {
        float acc = 0.f;
        #pragma unroll
        for (int w = 0; w < 8; w++) acc += s_maccw[w * 16 + tid];
        s_macc[tid] = acc;
    }
    __syncthreads();

    // node MLP: hidden = silu(NH + m_i @ node_w1[128:144] + b1)
    {
        float hv = g_NH[(size_t)bi * 256 + tid] + nb1[tid];
        #pragma unroll
        for (int c = 0; c < 16; c++) hv = fmaf(s_macc[c], nw1[(128 + c) * 256 + tid], hv);
        s_hid[tid] = silu_f(hv);
    }
    __syncthreads();
    // out = hidden @ node_w2 + b2 + feats (split-K)
    {
        int half = tid >> 7, dcol = tid & 127;
        const float* w2 = nw2 + half * 128 * 128 + dcol;
        const float* hh = s_hid + half * 128;
        float acc = 0.f;
        #pragma unroll 8
        for (int qq = 0; qq < 128; qq++) acc = fmaf(hh[qq], w2[qq * 128], acc);
        if (half == 0) s_out0[dcol] = acc; else s_out1[dcol] = acc;
    }
    __syncthreads();
    if (tid < 128) {
        out[(size_t)bi * 128 + tid] =
            s_out0[tid] + s_out1[tid] + nb2[tid] + feats[(size_t)bi * 128 + tid];
    }
    if (tid < 3) {
        float* outc = out + (size_t)NBI * DD;
        outc[(size_t)bi * 3 + tid] = coors[(size_t)bi * 3 + tid] + s_cacc[tid];
    }
}

extern "C" void kernel_launch(void* const* d_in, const int* in_sizes, int n_in,
                              void* d_out, int out_size) {
    const float* feats = (const float*)d_in[0];
    const float* coors = (const float*)d_in[1];
    const float* ew1   = (const float*)d_in[2];
    const float* eb1   = (const float*)d_in[3];
    const float* ew2   = (const float*)d_in[4];
    const float* eb2   = (const float*)d_in[5];
    const float* cw1   = (const float*)d_in[6];
    const float* cb1   = (const float*)d_in[7];
    const float* cw2   = (const float*)d_in[8];
    const float* cb2   = (const float*)d_in[9];
    const float* xw1   = (const float*)d_in[10];
    const float* xb1   = (const float*)d_in[11];
    const float* xw2   = (const float*)d_in[12];
    const float* xb2   = (const float*)d_in[13];
    const float* nw1   = (const float*)d_in[14];
    const float* nb1   = (const float*)d_in[15];
    const float* nw2   = (const float*)d_in[16];
    const float* nb2   = (const float*)d_in[17];
    float* out = (float*)d_out;

    cudaFuncSetAttribute(k_main, cudaFuncAttributeMaxDynamicSharedMemorySize, SMEM_BYTES);

    k_precomp<<<NBI / 64, 256>>>(feats, ew1, nw1);
    k_mean<<<NB, 256>>>(coors);
    k_topk<<<NBI, 256>>>(coors);
    k_main<<<NBI, 256, SMEM_BYTES>>>(feats, coors, ew1, eb1, ew2, eb2,
                                     cw1, cb1, cw2, cb2, xw1, xb1, xw2, xb2,
                                     nw1, nb1, nw2, nb2, out);
}

// round 7
// speedup vs baseline: 2.5479x; 1.0339x over previous
#include <cuda_runtime.h>
#include <math.h>

#define NB 4
#define NN 2048
#define DD 128
#define KK 32
#define H1 530      // 2*EIN
#define H1P 544     // padded to 17*32
#define NBI (NB*NN) // 8192

typedef unsigned long long ull;
typedef unsigned int uint;

// ---------------- scratch (static device globals; no allocation) ----------------
__device__ float g_A  [NBI * H1];         // feats_i @ W1[0:128]
__device__ float g_Bv [NBI * H1P + 160];  // feats_j @ W1[128:256], padded
__device__ float g_NH [NBI * 256];        // feats   @ node_w1[0:128]
__device__ float g_mi [NBI * 16];         // summed edge messages per node
__device__ float g_cm [NBI * 3];          // mean-centered coords
__device__ int   g_nbidx[NBI * KK];
__device__ float g_dk   [NBI * KK];

// ---------------- packed f32x2 primitives (Blackwell) ---------------------------
__device__ __forceinline__ ull pk2(float lo, float hi) {
    ull r; asm("mov.b64 %0,{%1,%2};" : "=l"(r) : "f"(lo), "f"(hi)); return r;
}
__device__ __forceinline__ void upk2(float& lo, float& hi, ull v) {
    asm("mov.b64 {%0,%1},%2;" : "=f"(lo), "=f"(hi) : "l"(v));
}
__device__ __forceinline__ ull fma2(ull a, ull b, ull c) {
    ull d; asm("fma.rn.f32x2 %0,%1,%2,%3;" : "=l"(d) : "l"(a), "l"(b), "l"(c)); return d;
}
__device__ __forceinline__ ull add2(ull a, ull b) {
    ull d; asm("add.rn.f32x2 %0,%1,%2;" : "=l"(d) : "l"(a), "l"(b)); return d;
}
__device__ __forceinline__ ull mul2(ull a, ull b) {
    ull d; asm("mul.rn.f32x2 %0,%1,%2;" : "=l"(d) : "l"(a), "l"(b)); return d;
}
__device__ __forceinline__ ull shflx64(ull v, int m) {
    uint lo, hi;
    asm("mov.b64 {%0,%1},%2;" : "=r"(lo), "=r"(hi) : "l"(v));
    lo = __shfl_xor_sync(0xffffffffu, lo, m);
    hi = __shfl_xor_sync(0xffffffffu, hi, m);
    ull r; asm("mov.b64 %0,{%1,%2};" : "=l"(r) : "r"(lo), "r"(hi)); return r;
}

// packed silu with exact scalar fallback for |x|>=1 (never taken in practice)
#define SILU2(res, xin) do { \
    ull _x = (xin); \
    ull _x2 = mul2(_x, _x); \
    ull _s = fma2(CP4, _x2, CP3); \
    _s = fma2(_s, _x2, CP2); \
    _s = fma2(_s, _x2, CP1); \
    _s = fma2(_s, _x2, CP0); \
    ull _t = fma2(_x, _s, CHALF); \
    (res) = mul2(_x, _t); \
    float _a, _b; upk2(_a, _b, _x); \
    if (fmaxf(fabsf(_a), fabsf(_b)) >= 1.0f) { \
        float _r0 = _a / (1.0f + __expf(-_a)); \
        float _r1 = _b / (1.0f + __expf(-_b)); \
        (res) = pk2(_r0, _r1); \
    } \
} while (0)

// ---------------- scalar fast SiLU -------------------------
__device__ __forceinline__ float silu_f(float x) {
    float ax = fabsf(x);
    if (ax < 1.0f) {
        float x2 = x * x;
        float s = 31.0f / 1451520.0f;
        s = fmaf(s, x2, -17.0f / 80640.0f);
        s = fmaf(s, x2,  1.0f / 480.0f);
        s = fmaf(s, x2, -1.0f / 48.0f);
        s = fmaf(s, x2,  0.25f);
        return x * fmaf(x, s, 0.5f);
    }
    return x / (1.0f + __expf(-x));
}

// ---------------- merged precompute: A, Bv, NH (packed f32x2 over col pairs) -----
__global__ void __launch_bounds__(256) k_precomp(const float* __restrict__ feats,
                                                 const float* __restrict__ ew1,
                                                 const float* __restrict__ nw1) {
    extern __shared__ float2 sfd[];   // 64 nodes x 128 feats, duplicated pairs
    int n0 = blockIdx.x * 64;
    int t = threadIdx.x;
    for (int idx = t; idx < 64 * 128; idx += 256) {
        float f = feats[(size_t)n0 * 128 + idx];
        sfd[idx] = make_float2(f, f);
    }
    __syncthreads();
    int ng = t >> 5, lane = t & 31;
    const ull* fd = (const ull*)sfd;
    int nb0 = ng * 8;

    // A / Bv: 265 col-pairs over 9 iterations
    #pragma unroll 1
    for (int it = 0; it < 9; it++) {
        int cp = it * 32 + lane;
        int cps = (cp < 265) ? cp : 264;
        ull a[8], bb[8];
        #pragma unroll
        for (int q = 0; q < 8; q++) { a[q] = 0ULL; bb[q] = 0ULL; }
        const float* wbase = ew1 + 2 * cps;
        #pragma unroll 4
        for (int d = 0; d < 128; d++) {
            ull wA = *(const ull*)(wbase + (size_t)d * H1);
            ull wB = *(const ull*)(wbase + (size_t)(128 + d) * H1);
            #pragma unroll
            for (int q = 0; q < 8; q++) {
                ull fv = fd[(nb0 + q) * 128 + d];
                a[q]  = fma2(fv, wA, a[q]);
                bb[q] = fma2(fv, wB, bb[q]);
            }
        }
        if (cp < 265) {
            #pragma unroll
            for (int q = 0; q < 8; q++) {
                int node = n0 + nb0 + q;
                *(ull*)&g_A [(size_t)node * H1  + 2 * cp] = a[q];
                *(ull*)&g_Bv[(size_t)node * H1P + 2 * cp] = bb[q];
            }
        }
    }

    // NH: 128 col-pairs over 4 iterations
    #pragma unroll 1
    for (int it = 0; it < 4; it++) {
        int cp = it * 32 + lane;
        ull a[8];
        #pragma unroll
        for (int q = 0; q < 8; q++) a[q] = 0ULL;
        const float* wbase = nw1 + 2 * cp;
        #pragma unroll 4
        for (int d = 0; d < 128; d++) {
            ull w = *(const ull*)(wbase + (size_t)d * 256);
            #pragma unroll
            for (int q = 0; q < 8; q++)
                a[q] = fma2(fd[(nb0 + q) * 128 + d], w, a[q]);
        }
        #pragma unroll
        for (int q = 0; q < 8; q++)
            *(ull*)&g_NH[(size_t)(n0 + nb0 + q) * 256 + 2 * cp] = a[q];
    }
}

// ---------------- mean-center coords ----------------
__global__ void __launch_bounds__(256) k_mean(const float* __restrict__ coors) {
    int b = blockIdx.x, t = threadIdx.x;
    __shared__ float rx[256], ry[256], rz[256];
    const float* cb = coors + (size_t)b * NN * 3;
    float sx = 0.f, sy = 0.f, sz = 0.f;
    for (int j = t; j < NN; j += 256) {
        sx += cb[3 * j]; sy += cb[3 * j + 1]; sz += cb[3 * j + 2];
    }
    rx[t] = sx; ry[t] = sy; rz[t] = sz;
    __syncthreads();
    for (int s = 128; s > 0; s >>= 1) {
        if (t < s) { rx[t] += rx[t + s]; ry[t] += ry[t + s]; rz[t] += rz[t + s]; }
        __syncthreads();
    }
    float mx = rx[0] * (1.0f / NN), my = ry[0] * (1.0f / NN), mz = rz[0] * (1.0f / NN);
    float* cmb = g_cm + (size_t)b * NN * 3;
    for (int j = t; j < NN; j += 256) {
        cmb[3 * j]     = cb[3 * j]     - mx;
        cmb[3 * j + 1] = cb[3 * j + 1] - my;
        cmb[3 * j + 2] = cb[3 * j + 2] - mz;
    }
}

// ---------------- top-K: binary search on float bit-keys in registers ------------
__global__ void __launch_bounds__(256) k_topk(const float* __restrict__ coors) {
    int bi = blockIdx.x;
    int b  = bi >> 11;
    int t = threadIdx.x, lane = t & 31, wid = t >> 5;
    __shared__ int s_cnt[8];
    __shared__ unsigned s_loS, s_hiS, s_thr;
    __shared__ int s_done, s_sel, s_curmin;

    const float* cb = coors + (size_t)b * NN * 3;
    float cx = coors[(size_t)bi * 3], cy = coors[(size_t)bi * 3 + 1], cz = coors[(size_t)bi * 3 + 2];
    float d[8]; unsigned ud[8];
    #pragma unroll
    for (int i = 0; i < 8; i++) {
        int j = t + i * 256;
        float dx = cx - cb[3 * j], dy = cy - cb[3 * j + 1], dz = cz - cb[3 * j + 2];
        float dv = dx * dx + dy * dy + dz * dz;
        d[i] = dv; ud[i] = __float_as_uint(dv);
    }
    if (t == 0) { s_loS = 0u; s_hiS = 0x7f800000u; s_done = 0; s_sel = 0; s_curmin = -1; }
    __syncthreads();

    #pragma unroll 1
    for (int it = 0; it < 34; it++) {
        unsigned lo = s_loS, hi = s_hiS;
        unsigned mid = lo + ((hi - lo) >> 1);
        int c = 0;
        #pragma unroll
        for (int i = 0; i < 8; i++) c += (ud[i] <= mid) ? 1 : 0;
        #pragma unroll
        for (int off = 16; off; off >>= 1) c += __shfl_xor_sync(0xffffffffu, c, off);
        if (lane == 0) s_cnt[wid] = c;
        __syncthreads();
        if (t == 0) {
            int tot = 0;
            #pragma unroll
            for (int w = 0; w < 8; w++) tot += s_cnt[w];
            if (tot == KK) { s_thr = mid; s_done = 1; }
            else {
                unsigned nlo = lo, nhi = hi;
                if (tot > KK) nhi = mid; else nlo = mid + 1;
                if (nlo >= nhi) { s_thr = nlo; s_done = 2; }
                s_loS = nlo; s_hiS = nhi;
            }
        }
        __syncthreads();
        if (s_done) break;
    }
    unsigned thr = s_thr; int mode = s_done;

    #pragma unroll
    for (int i = 0; i < 8; i++) {
        bool sel = (mode == 1) ? (ud[i] <= thr) : (ud[i] < thr);
        if (sel) {
            int p = atomicAdd(&s_sel, 1);
            g_nbidx[(size_t)bi * KK + p] = t + i * 256;
            g_dk   [(size_t)bi * KK + p] = d[i];
        }
    }
    __syncthreads();
    if (mode == 2) {
        int C = s_sel;
        for (int k = C; k < KK; k++) {
            int prev = s_curmin;
            int cand = 0x7fffffff;
            #pragma unroll
            for (int i = 0; i < 8; i++) {
                int j = t + i * 256;
                if (ud[i] == thr && j > prev && j < cand) cand = j;
            }
            #pragma unroll
            for (int off = 16; off; off >>= 1) {
                int o = __shfl_xor_sync(0xffffffffu, cand, off);
                cand = min(cand, o);
            }
            if (lane == 0) s_cnt[wid] = cand;
            __syncthreads();
            if (t == 0) {
                int mn = s_cnt[0];
                #pragma unroll
                for (int w = 1; w < 8; w++) mn = min(mn, s_cnt[w]);
                g_nbidx[(size_t)bi * KK + k] = mn;
                g_dk   [(size_t)bi * KK + k] = __uint_as_float(thr);
                s_curmin = mn;
            }
            __syncthreads();
        }
    }
}

// ---------------- 64-bit packed reduce-scatter step -----------------------------
template <int MASK, int HALF>
__device__ __forceinline__ void rstep64(ull* q, int lane) {
    bool hi = (lane & MASK) != 0;
    #pragma unroll
    for (int i = 0; i < HALF; i++) {
        ull sent = hi ? q[i] : q[HALF + i];
        ull recv = shflx64(sent, MASK);
        q[i] = add2(hi ? q[HALF + i] : q[i], recv);
    }
}

// ---------------- smem layout (floats) for k_main --------------------------------
#define O_BASE 0
#define O_W1Q  544                 // 2 quads * H1P * 4 = 4352
#define O_W1R  (O_W1Q + 4352)      // pair (row8, 0) * H1P * 2 = 1088
#define O_W2Q  (O_W1R + 1088)      // 4 quads * H1P * 4 = 8704
#define O_CXW1 (O_W2Q + 8704)      // [c][l] (cw1|xw1) pairs: 16*64*2 = 2048
#define O_CXB1 (O_CXW1 + 2048)     // 128
#define O_CXW2 (O_CXB1 + 128)      // 128
#define O_B2   (O_CXW2 + 128)      // 16
#define O_ENC  (O_B2 + 16)         // 288
#define O_M    (O_ENC + 288)       // 8 warps * 32
#define O_MD   (O_M + 256)         // duplicated m pairs: 8 warps * 32 * 2 = 512
#define O_MACW (O_MD + 512)        // 128
#define O_CACC (O_MACW + 128)      // 4
#define O_GEO  (O_CACC + 4)        // 8
#define O_NB   (O_GEO + 8)         // 32 ints
#define SMEM_FLOATS (O_NB + 32)
#define SMEM_BYTES (SMEM_FLOATS * 4)

// ---------------- fused edge MLP + coord update ----------------------------------
__global__ void __launch_bounds__(256, 2) k_main(
    const float* __restrict__ coors,
    const float* __restrict__ ew1,  const float* __restrict__ eb1,
    const float* __restrict__ ew2,  const float* __restrict__ eb2,
    const float* __restrict__ cw1g, const float* __restrict__ cb1g,
    const float* __restrict__ cw2g, const float* __restrict__ cb2g,
    const float* __restrict__ xw1g, const float* __restrict__ xb1g,
    const float* __restrict__ xw2g, const float* __restrict__ xb2g,
    float* __restrict__ out)
{
    extern __shared__ float smx[];
    float* s_base = smx + O_BASE;
    float* s_w1q  = smx + O_W1Q;
    float* s_w1r  = smx + O_W1R;
    float* s_w2q  = smx + O_W2Q;
    float* s_cxw1 = smx + O_CXW1;
    float* s_cxb1 = smx + O_CXB1;
    float* s_cxw2 = smx + O_CXW2;
    float* s_b2   = smx + O_B2;
    float* s_enc  = smx + O_ENC;
    float* s_m    = smx + O_M;
    float* s_maccw= smx + O_MACW;
    float* s_cacc = smx + O_CACC;
    float* s_geo  = smx + O_GEO;
    int*   s_nb   = (int*)(smx + O_NB);

    int tid = threadIdx.x;
    int bi  = blockIdx.x;
    int b   = bi >> 11;

    // ---- prologue ----
    for (int c = tid; c < H1P; c += 256)
        s_base[c] = (c < H1) ? (g_A[(size_t)bi * H1 + c] + eb1[c]) : 0.f;
    for (int idx = tid; idx < 4352; idx += 256) {
        int e4 = idx >> 2, f = idx & 3;
        int qi = e4 / H1P, el = e4 - qi * H1P;
        int r = qi * 4 + f;
        s_w1q[idx] = (el < H1) ? ew1[(size_t)(256 + r) * H1 + el] : 0.f;
    }
    for (int idx = tid; idx < 1088; idx += 256) {
        int el = idx >> 1, f = idx & 1;
        s_w1r[idx] = (el < H1 && f == 0) ? ew1[(size_t)264 * H1 + el] : 0.f;
    }
    for (int idx = tid; idx < 8704; idx += 256) {
        int e4 = idx >> 2, f = idx & 3;
        int cq = e4 / H1P, el = e4 - cq * H1P;
        s_w2q[idx] = (el < H1) ? ew2[(size_t)el * 16 + cq * 4 + f] : 0.f;
    }
    for (int idx = tid; idx < 2048; idx += 256) {
        int p = idx >> 1, w = idx & 1;
        int c = p >> 6, l = p & 63;
        s_cxw1[idx] = w ? xw1g[c * 64 + l] : cw1g[c * 64 + l];
    }
    if (tid < 128) {
        int l = tid >> 1, w = tid & 1;
        s_cxb1[tid] = w ? xb1g[l] : cb1g[l];
        s_cxw2[tid] = w ? xw2g[l] : cw2g[l];
    }
    if (tid < 16) s_b2[tid] = eb2[tid];
    if (tid < 4)  s_cacc[tid] = 0.f;
    if (tid < 32) {
        float dv = g_dk[(size_t)bi * KK + tid];
        s_enc[tid * 9 + 0] = sinf(dv);
        s_enc[tid * 9 + 1] = sinf(0.5f * dv);
        s_enc[tid * 9 + 2] = sinf(0.25f * dv);
        s_enc[tid * 9 + 3] = sinf(0.125f * dv);
        s_enc[tid * 9 + 4] = cosf(dv);
        s_enc[tid * 9 + 5] = cosf(0.5f * dv);
        s_enc[tid * 9 + 6] = cosf(0.25f * dv);
        s_enc[tid * 9 + 7] = cosf(0.125f * dv);
        s_enc[tid * 9 + 8] = dv;
        s_nb[tid] = g_nbidx[(size_t)bi * KK + tid];
    }
    if (tid < 3) { s_geo[tid] = coors[(size_t)bi * 3 + tid]; s_geo[3 + tid] = g_cm[(size_t)bi * 3 + tid]; }
    __syncthreads();

    int lane = tid & 31, wid = tid >> 5;
    float cb2r = cb2g[0], xb2r = xb2g[0];
    float ci0 = s_geo[0], ci1 = s_geo[1], ci2 = s_geo[2];
    float ai0 = s_geo[3], ai1 = s_geo[4], ai2 = s_geo[5];
    const float* cb3 = coors + (size_t)b * NN * 3;
    const float* cmb = g_cm  + (size_t)b * NN * 3;

    const ulonglong2* w1q64 = (const ulonglong2*)s_w1q;  // [qi*H1P + el]
    const ull* w1r64 = (const ull*)s_w1r;                // [el]
    const ulonglong2* w2q64 = (const ulonglong2*)s_w2q;  // [cq*H1P + el]
    const ull* b2_64  = (const ull*)s_b2;
    ull* sm64  = (ull*)s_m;
    ull* smd64 = (ull*)(smx + O_MD);
    const ull* cxw1_64 = (const ull*)s_cxw1;
    const ull* cxb1_64 = (const ull*)s_cxb1;
    const ull* cxw2_64 = (const ull*)s_cxw2;

    const ull CP4 = pk2(31.0f / 1451520.0f, 31.0f / 1451520.0f);
    const ull CP3 = pk2(-17.0f / 80640.0f, -17.0f / 80640.0f);
    const ull CP2 = pk2(1.0f / 480.0f, 1.0f / 480.0f);
    const ull CP1 = pk2(-1.0f / 48.0f, -1.0f / 48.0f);
    const ull CP0 = pk2(0.25f, 0.25f);
    const ull CHALF = pk2(0.5f, 0.5f);

    float caccl = 0.f;
    float maccr = 0.f;

    #pragma unroll 1
    for (int pass = 0; pass < 2; pass++) {
        int e0 = pass * 16 + wid * 2;
        int j0 = s_nb[e0], j1 = s_nb[e0 + 1];
        const float* bv0 = g_Bv + ((size_t)b * NN + j0) * H1P;
        const float* bv1 = g_Bv + ((size_t)b * NN + j1) * H1P;
        ull e92a[5], e92b[5];
        #pragma unroll
        for (int rp = 0; rp < 5; rp++) {
            float a0 = s_enc[e0 * 9 + 2 * rp];
            float a1 = (2 * rp + 1 < 9) ? s_enc[e0 * 9 + 2 * rp + 1] : 0.f;
            float b0 = s_enc[(e0 + 1) * 9 + 2 * rp];
            float b1 = (2 * rp + 1 < 9) ? s_enc[(e0 + 1) * 9 + 2 * rp + 1] : 0.f;
            e92a[rp] = pk2(a0, a1);
            e92b[rp] = pk2(b0, b1);
        }

        ull q[16];
        #pragma unroll
        for (int i = 0; i < 16; i++) q[i] = 0ULL;

        // 2-deep Bv prefetch (global pad covers overruns)
        float bc0 = bv0[lane],      bc1 = bv1[lane];
        float bn0 = bv0[lane + 32], bn1 = bv1[lane + 32];
        #pragma unroll 1
        for (int tt = 0; tt < 17; tt++) {
            int el = tt * 32 + lane;
            float bf0 = bv0[el + 64];
            float bf1 = bv1[el + 64];
            float base = s_base[el];
            ulonglong2 wa = w1q64[el];
            ulonglong2 wb = w1q64[H1P + el];
            ull wc = w1r64[el];
            ull s0 = mul2(e92a[0], wa.x);
            s0 = fma2(e92a[1], wa.y, s0);
            s0 = fma2(e92a[2], wb.x, s0);
            s0 = fma2(e92a[3], wb.y, s0);
            s0 = fma2(e92a[4], wc,   s0);
            ull s1 = mul2(e92b[0], wa.x);
            s1 = fma2(e92b[1], wa.y, s1);
            s1 = fma2(e92b[2], wb.x, s1);
            s1 = fma2(e92b[3], wb.y, s1);
            s1 = fma2(e92b[4], wc,   s1);
            float p0, p1, r0, r1;
            upk2(p0, p1, s0);
            upk2(r0, r1, s1);
            float a0 = base + bc0 + p0 + p1;
            float a1 = base + bc1 + r0 + r1;
            ull h; SILU2(h, pk2(a0, a1));
            float h0, h1; upk2(h0, h1, h);
            ull h0d = pk2(h0, h0), h1d = pk2(h1, h1);
            #pragma unroll
            for (int cq = 0; cq < 4; cq++) {
                ulonglong2 w2 = w2q64[cq * H1P + el];
                q[2 * cq]     = fma2(h0d, w2.x, q[2 * cq]);
                q[2 * cq + 1] = fma2(h0d, w2.y, q[2 * cq + 1]);
                q[8 + 2 * cq]     = fma2(h1d, w2.x, q[8 + 2 * cq]);
                q[8 + 2 * cq + 1] = fma2(h1d, w2.y, q[8 + 2 * cq + 1]);
            }
            bc0 = bn0; bc1 = bn1; bn0 = bf0; bn1 = bf1;
        }

        // packed reduce-scatter: lane (lane>>1)&15 owns pair id = e*8 + c2
        rstep64<16, 8>(q, lane);
        rstep64<8, 4>(q, lane);
        rstep64<4, 2>(q, lane);
        rstep64<2, 1>(q, lane);
        q[0] = add2(q[0], shflx64(q[0], 1));

        {
            int idx = (lane >> 1) & 15;
            int e = idx >> 3, c2 = idx & 7;
            ull mb; SILU2(mb, add2(q[0], b2_64[c2]));
            if ((lane & 1) == 0) {
                sm64[wid * 16 + e * 8 + c2] = mb;
                float m0, m1; upk2(m0, m1, mb);
                smd64[wid * 32 + e * 16 + 2 * c2]     = pk2(m0, m0);
                smd64[wid * 32 + e * 16 + 2 * c2 + 1] = pk2(m1, m1);
            }
        }
        __syncwarp();
        if (lane < 16) maccr += s_m[wid * 32 + lane] + s_m[wid * 32 + 16 + lane];

        // coor + cross MLPs packed as (coor|cross) pairs
        #pragma unroll 1
        for (int e = 0; e < 2; e++) {
            const ull* md = smd64 + wid * 32 + e * 16;
            ull hP0 = cxb1_64[lane];
            ull hP1 = cxb1_64[lane + 32];
            #pragma unroll
            for (int c = 0; c < 16; c++) {
                ull mdc = md[c];
                hP0 = fma2(mdc, cxw1_64[c * 64 + lane],      hP0);
                hP1 = fma2(mdc, cxw1_64[c * 64 + lane + 32], hP1);
            }
            ull sA, sB;
            SILU2(sA, hP0);
            SILU2(sB, hP1);
            ull tt2 = mul2(sA, cxw2_64[lane]);
            tt2 = fma2(sB, cxw2_64[lane + 32], tt2);
            #pragma unroll
            for (int off = 16; off > 0; off >>= 1)
                tt2 = add2(tt2, shflx64(tt2, off));
            float cw, xw; upk2(cw, xw, tt2);
            cw += cb2r; xw += xb2r;

            int j = (e == 0) ? j0 : j1;
            float cj0 = cb3[3 * j], cj1 = cb3[3 * j + 1], cj2 = cb3[3 * j + 2];
            float bj0 = cmb[3 * j], bj1 = cmb[3 * j + 1], bj2 = cmb[3 * j + 2];
            float rr, xx;
            if (lane == 0)      { rr = ci0 - cj0; xx = ai1 * bj2 - ai2 * bj1; }
            else if (lane == 1) { rr = ci1 - cj1; xx = ai2 * bj0 - ai0 * bj2; }
            else                { rr = ci2 - cj2; xx = ai0 * bj1 - ai1 * bj0; }
            if (lane < 3) caccl = fmaf(cw, rr, fmaf(xw, xx, caccl));
        }
    }
    if (lane < 16) s_maccw[wid * 16 + lane] = maccr;
    if (lane < 3) atomicAdd(&s_cacc[lane], caccl);
    __syncthreads();

    if (tid < 16) {
        float acc = 0.f;
        #pragma unroll
        for (int w = 0; w < 8; w++) acc += s_maccw[w * 16 + tid];
        g_mi[(size_t)bi * 16 + tid] = acc;
    }
    if (tid < 3) {
        float* outc = out + (size_t)NBI * DD;
        outc[(size_t)bi * 3 + tid] = coors[(size_t)bi * 3 + tid] + s_cacc[tid];
    }
}

// ---------------- node MLP: 16 nodes per block -----------------------------------
__global__ void __launch_bounds__(256) k_node(
    const float* __restrict__ feats,
    const float* __restrict__ nw1, const float* __restrict__ nb1,
    const float* __restrict__ nw2, const float* __restrict__ nb2,
    float* __restrict__ out)
{
    __shared__ float s_nw1[16 * 256];
    __shared__ float s_m[16 * 16];
    __shared__ float s_hid[16 * 256];
    int n0 = blockIdx.x * 16;
    int tid = threadIdx.x;

    for (int idx = tid; idx < 4096; idx += 256) {
        int c = idx >> 8, col = idx & 255;
        s_nw1[idx] = nw1[(size_t)(128 + c) * 256 + col];
    }
    s_m[tid] = g_mi[(size_t)n0 * 16 + tid];
    __syncthreads();

    // hidden = silu(NH + m @ nw1[128:144] + b1)
    {
        float bcol = nb1[tid];
        #pragma unroll 1
        for (int node = 0; node < 16; node++) {
            float hv = g_NH[(size_t)(n0 + node) * 256 + tid] + bcol;
            #pragma unroll
            for (int c = 0; c < 16; c++)
                hv = fmaf(s_m[node * 16 + c], s_nw1[c * 256 + tid], hv);
            s_hid[node * 256 + tid] = silu_f(hv);
        }
    }
    __syncthreads();

    // out = hidden @ nw2 + b2 + feats ; 8 nodes per thread-half
    {
        int col = tid & 127, g = tid >> 7;
        const float* hh = s_hid + g * 8 * 256;
        float acc[8];
        #pragma unroll
        for (int nn = 0; nn < 8; nn++) acc[nn] = 0.f;
        #pragma unroll 4
        for (int k = 0; k < 256; k++) {
            float w = nw2[(size_t)k * 128 + col];
            #pragma unroll
            for (int nn = 0; nn < 8; nn++)
                acc[nn] = fmaf(hh[nn * 256 + k], w, acc[nn]);
        }
        float bb = nb2[col];
        #pragma unroll
        for (int nn = 0; nn < 8; nn++) {
            int node = n0 + g * 8 + nn;
            out[(size_t)node * 128 + col] = acc[nn] + bb + feats[(size_t)node * 128 + col];
        }
    }
}

extern "C" void kernel_launch(void* const* d_in, const int* in_sizes, int n_in,
                              void* d_out, int out_size) {
    const float* feats = (const float*)d_in[0];
    const float* coors = (const float*)d_in[1];
    const float* ew1   = (const float*)d_in[2];
    const float* eb1   = (const float*)d_in[3];
    const float* ew2   = (const float*)d_in[4];
    const float* eb2   = (const float*)d_in[5];
    const float* cw1   = (const float*)d_in[6];
    const float* cb1   = (const float*)d_in[7];
    const float* cw2   = (const float*)d_in[8];
    const float* cb2   = (const float*)d_in[9];
    const float* xw1   = (const float*)d_in[10];
    const float* xb1   = (const float*)d_in[11];
    const float* xw2   = (const float*)d_in[12];
    const float* xb2   = (const float*)d_in[13];
    const float* nw1   = (const float*)d_in[14];
    const float* nb1   = (const float*)d_in[15];
    const float* nw2   = (const float*)d_in[16];
    const float* nb2   = (const float*)d_in[17];
    float* out = (float*)d_out;

    cudaFuncSetAttribute(k_main, cudaFuncAttributeMaxDynamicSharedMemorySize, SMEM_BYTES);
    cudaFuncSetAttribute(k_precomp, cudaFuncAttributeMaxDynamicSharedMemorySize, 65536);

    k_precomp<<<NBI / 64, 256, 65536>>>(feats, ew1, nw1);
    k_mean<<<NB, 256>>>(coors);
    k_topk<<<NBI, 256>>>(coors);
    k_main<<<NBI, 256, SMEM_BYTES>>>(coors, ew1, eb1, ew2, eb2,
                                     cw1, cb1, cw2, cb2, xw1, xb1, xw2, xb2, out);
    k_node<<<NBI / 16, 256>>>(feats, nw1, nb1, nw2, nb2, out);
}

// round 8
// speedup vs baseline: 2.8689x; 1.1260x over previous
#include <cuda_runtime.h>
#include <math.h>

#define NB 4
#define NN 2048
#define DD 128
#define KK 32
#define H1 530      // 2*EIN
#define H1P 544     // padded to 17*32
#define NBI (NB*NN) // 8192
#define NODES_PER_BLK 16

typedef unsigned long long ull;
typedef unsigned int uint;

// ---------------- scratch (static device globals; no allocation) ----------------
__device__ float g_A  [NBI * H1];         // feats_i @ W1[0:128]
__device__ float g_Bv [NBI * H1P + 160];  // feats_j @ W1[128:256], padded
__device__ float g_NH [NBI * 256];        // feats   @ node_w1[0:128]
__device__ float g_mi [NBI * 16];         // summed edge messages per node
__device__ float g_cm [NBI * 3];          // mean-centered coords
__device__ int   g_nbidx[NBI * KK];
__device__ float g_dk   [NBI * KK];

// ---------------- packed f32x2 primitives (Blackwell) ---------------------------
__device__ __forceinline__ ull pk2(float lo, float hi) {
    ull r; asm("mov.b64 %0,{%1,%2};" : "=l"(r) : "f"(lo), "f"(hi)); return r;
}
__device__ __forceinline__ void upk2(float& lo, float& hi, ull v) {
    asm("mov.b64 {%0,%1},%2;" : "=f"(lo), "=f"(hi) : "l"(v));
}
__device__ __forceinline__ ull fma2(ull a, ull b, ull c) {
    ull d; asm("fma.rn.f32x2 %0,%1,%2,%3;" : "=l"(d) : "l"(a), "l"(b), "l"(c)); return d;
}
__device__ __forceinline__ ull add2(ull a, ull b) {
    ull d; asm("add.rn.f32x2 %0,%1,%2;" : "=l"(d) : "l"(a), "l"(b)); return d;
}
__device__ __forceinline__ ull mul2(ull a, ull b) {
    ull d; asm("mul.rn.f32x2 %0,%1,%2;" : "=l"(d) : "l"(a), "l"(b)); return d;
}
__device__ __forceinline__ ull shflx64(ull v, int m) {
    uint lo, hi;
    asm("mov.b64 {%0,%1},%2;" : "=r"(lo), "=r"(hi) : "l"(v));
    lo = __shfl_xor_sync(0xffffffffu, lo, m);
    hi = __shfl_xor_sync(0xffffffffu, hi, m);
    ull r; asm("mov.b64 %0,{%1,%2};" : "=l"(r) : "r"(lo), "r"(hi)); return r;
}

// packed silu with exact scalar fallback for |x|>=1 (never taken in practice)
#define SILU2(res, xin) do { \
    ull _x = (xin); \
    ull _x2 = mul2(_x, _x); \
    ull _s = fma2(CP4, _x2, CP3); \
    _s = fma2(_s, _x2, CP2); \
    _s = fma2(_s, _x2, CP1); \
    _s = fma2(_s, _x2, CP0); \
    ull _t = fma2(_x, _s, CHALF); \
    (res) = mul2(_x, _t); \
    float _a, _b; upk2(_a, _b, _x); \
    if (fmaxf(fabsf(_a), fabsf(_b)) >= 1.0f) { \
        float _r0 = _a / (1.0f + __expf(-_a)); \
        float _r1 = _b / (1.0f + __expf(-_b)); \
        (res) = pk2(_r0, _r1); \
    } \
} while (0)

// ---------------- scalar fast SiLU -------------------------
__device__ __forceinline__ float silu_f(float x) {
    float ax = fabsf(x);
    if (ax < 1.0f) {
        float x2 = x * x;
        float s = 31.0f / 1451520.0f;
        s = fmaf(s, x2, -17.0f / 80640.0f);
        s = fmaf(s, x2,  1.0f / 480.0f);
        s = fmaf(s, x2, -1.0f / 48.0f);
        s = fmaf(s, x2,  0.25f);
        return x * fmaf(x, s, 0.5f);
    }
    return x / (1.0f + __expf(-x));
}

// ---------------- merged precompute: A, Bv, NH (packed f32x2 over col pairs) -----
__global__ void __launch_bounds__(256) k_precomp(const float* __restrict__ feats,
                                                 const float* __restrict__ ew1,
                                                 const float* __restrict__ nw1) {
    extern __shared__ float2 sfd[];   // 64 nodes x 128 feats, duplicated pairs
    int n0 = blockIdx.x * 64;
    int t = threadIdx.x;
    for (int idx = t; idx < 64 * 128; idx += 256) {
        float f = feats[(size_t)n0 * 128 + idx];
        sfd[idx] = make_float2(f, f);
    }
    __syncthreads();
    int ng = t >> 5, lane = t & 31;
    const ull* fd = (const ull*)sfd;
    int nb0 = ng * 8;

    // A / Bv: 265 col-pairs over 9 iterations
    #pragma unroll 1
    for (int it = 0; it < 9; it++) {
        int cp = it * 32 + lane;
        int cps = (cp < 265) ? cp : 264;
        ull a[8], bb[8];
        #pragma unroll
        for (int q = 0; q < 8; q++) { a[q] = 0ULL; bb[q] = 0ULL; }
        const float* wbase = ew1 + 2 * cps;
        #pragma unroll 4
        for (int d = 0; d < 128; d++) {
            ull wA = *(const ull*)(wbase + (size_t)d * H1);
            ull wB = *(const ull*)(wbase + (size_t)(128 + d) * H1);
            #pragma unroll
            for (int q = 0; q < 8; q++) {
                ull fv = fd[(nb0 + q) * 128 + d];
                a[q]  = fma2(fv, wA, a[q]);
                bb[q] = fma2(fv, wB, bb[q]);
            }
        }
        if (cp < 265) {
            #pragma unroll
            for (int q = 0; q < 8; q++) {
                int node = n0 + nb0 + q;
                *(ull*)&g_A [(size_t)node * H1  + 2 * cp] = a[q];
                *(ull*)&g_Bv[(size_t)node * H1P + 2 * cp] = bb[q];
            }
        }
    }

    // NH: 128 col-pairs over 4 iterations
    #pragma unroll 1
    for (int it = 0; it < 4; it++) {
        int cp = it * 32 + lane;
        ull a[8];
        #pragma unroll
        for (int q = 0; q < 8; q++) a[q] = 0ULL;
        const float* wbase = nw1 + 2 * cp;
        #pragma unroll 4
        for (int d = 0; d < 128; d++) {
            ull w = *(const ull*)(wbase + (size_t)d * 256);
            #pragma unroll
            for (int q = 0; q < 8; q++)
                a[q] = fma2(fd[(nb0 + q) * 128 + d], w, a[q]);
        }
        #pragma unroll
        for (int q = 0; q < 8; q++)
            *(ull*)&g_NH[(size_t)(n0 + nb0 + q) * 256 + 2 * cp] = a[q];
    }
}

// ---------------- mean-center coords ----------------
__global__ void __launch_bounds__(256) k_mean(const float* __restrict__ coors) {
    int b = blockIdx.x, t = threadIdx.x;
    __shared__ float rx[256], ry[256], rz[256];
    const float* cb = coors + (size_t)b * NN * 3;
    float sx = 0.f, sy = 0.f, sz = 0.f;
    for (int j = t; j < NN; j += 256) {
        sx += cb[3 * j]; sy += cb[3 * j + 1]; sz += cb[3 * j + 2];
    }
    rx[t] = sx; ry[t] = sy; rz[t] = sz;
    __syncthreads();
    for (int s = 128; s > 0; s >>= 1) {
        if (t < s) { rx[t] += rx[t + s]; ry[t] += ry[t + s]; rz[t] += rz[t + s]; }
        __syncthreads();
    }
    float mx = rx[0] * (1.0f / NN), my = ry[0] * (1.0f / NN), mz = rz[0] * (1.0f / NN);
    float* cmb = g_cm + (size_t)b * NN * 3;
    for (int j = t; j < NN; j += 256) {
        cmb[3 * j]     = cb[3 * j]     - mx;
        cmb[3 * j + 1] = cb[3 * j + 1] - my;
        cmb[3 * j + 2] = cb[3 * j + 2] - mz;
    }
}

// ---------------- top-K: binary search on float bit-keys in registers ------------
__global__ void __launch_bounds__(256) k_topk(const float* __restrict__ coors) {
    int bi = blockIdx.x;
    int b  = bi >> 11;
    int t = threadIdx.x, lane = t & 31, wid = t >> 5;
    __shared__ int s_cnt[8];
    __shared__ unsigned s_loS, s_hiS, s_thr;
    __shared__ int s_done, s_sel, s_curmin;

    const float* cb = coors + (size_t)b * NN * 3;
    float cx = coors[(size_t)bi * 3], cy = coors[(size_t)bi * 3 + 1], cz = coors[(size_t)bi * 3 + 2];
    float d[8]; unsigned ud[8];
    #pragma unroll
    for (int i = 0; i < 8; i++) {
        int j = t + i * 256;
        float dx = cx - cb[3 * j], dy = cy - cb[3 * j + 1], dz = cz - cb[3 * j + 2];
        float dv = dx * dx + dy * dy + dz * dz;
        d[i] = dv; ud[i] = __float_as_uint(dv);
    }
    if (t == 0) { s_loS = 0u; s_hiS = 0x7f800000u; s_done = 0; s_sel = 0; s_curmin = -1; }
    __syncthreads();

    #pragma unroll 1
    for (int it = 0; it < 34; it++) {
        unsigned lo = s_loS, hi = s_hiS;
        unsigned mid = lo + ((hi - lo) >> 1);
        int c = 0;
        #pragma unroll
        for (int i = 0; i < 8; i++) c += (ud[i] <= mid) ? 1 : 0;
        #pragma unroll
        for (int off = 16; off; off >>= 1) c += __shfl_xor_sync(0xffffffffu, c, off);
        if (lane == 0) s_cnt[wid] = c;
        __syncthreads();
        if (t == 0) {
            int tot = 0;
            #pragma unroll
            for (int w = 0; w < 8; w++) tot += s_cnt[w];
            if (tot == KK) { s_thr = mid; s_done = 1; }
            else {
                unsigned nlo = lo, nhi = hi;
                if (tot > KK) nhi = mid; else nlo = mid + 1;
                if (nlo >= nhi) { s_thr = nlo; s_done = 2; }
                s_loS = nlo; s_hiS = nhi;
            }
        }
        __syncthreads();
        if (s_done) break;
    }
    unsigned thr = s_thr; int mode = s_done;

    #pragma unroll
    for (int i = 0; i < 8; i++) {
        bool sel = (mode == 1) ? (ud[i] <= thr) : (ud[i] < thr);
        if (sel) {
            int p = atomicAdd(&s_sel, 1);
            g_nbidx[(size_t)bi * KK + p] = t + i * 256;
            g_dk   [(size_t)bi * KK + p] = d[i];
        }
    }
    __syncthreads();
    if (mode == 2) {
        int C = s_sel;
        for (int k = C; k < KK; k++) {
            int prev = s_curmin;
            int cand = 0x7fffffff;
            #pragma unroll
            for (int i = 0; i < 8; i++) {
                int j = t + i * 256;
                if (ud[i] == thr && j > prev && j < cand) cand = j;
            }
            #pragma unroll
            for (int off = 16; off; off >>= 1) {
                int o = __shfl_xor_sync(0xffffffffu, cand, off);
                cand = min(cand, o);
            }
            if (lane == 0) s_cnt[wid] = cand;
            __syncthreads();
            if (t == 0) {
                int mn = s_cnt[0];
                #pragma unroll
                for (int w = 1; w < 8; w++) mn = min(mn, s_cnt[w]);
                g_nbidx[(size_t)bi * KK + k] = mn;
                g_dk   [(size_t)bi * KK + k] = __uint_as_float(thr);
                s_curmin = mn;
            }
            __syncthreads();
        }
    }
}

// ---------------- 64-bit packed reduce-scatter step -----------------------------
template <int MASK, int HALF>
__device__ __forceinline__ void rstep64(ull* q, int lane) {
    bool hi = (lane & MASK) != 0;
    #pragma unroll
    for (int i = 0; i < HALF; i++) {
        ull sent = hi ? q[i] : q[HALF + i];
        ull recv = shflx64(sent, MASK);
        q[i] = add2(hi ? q[HALF + i] : q[i], recv);
    }
}

// ---------------- smem layout (floats) for k_main --------------------------------
#define O_W1Q  0                   // 2 quads * H1P * 4 = 4352
#define O_W1R  (O_W1Q + 4352)      // pair (row8, 0) * H1P * 2 = 1088
#define O_W2Q  (O_W1R + 1088)      // 4 quads * H1P * 4 = 8704
#define O_CXW1 (O_W2Q + 8704)      // (cw1|xw1) pairs: 16*64*2 = 2048
#define O_CXB1 (O_CXW1 + 2048)     // 128
#define O_CXW2 (O_CXB1 + 128)      // 128
#define O_B2   (O_CXW2 + 128)      // 16
#define O_BASE (O_B2 + 16)         // 544
#define O_ENC  (O_BASE + 544)      // 288
#define O_M    (O_ENC + 288)       // 8 warps * 32
#define O_MD   (O_M + 256)         // duplicated m pairs: 512
#define O_MACW (O_MD + 512)        // 128
#define O_CACC (O_MACW + 128)      // 4
#define O_GEO  (O_CACC + 4)        // 8
#define O_NB   (O_GEO + 8)         // 32 ints
#define SMEM_FLOATS (O_NB + 32)
#define SMEM_BYTES (SMEM_FLOATS * 4)

// ---------------- fused edge MLP + coord update (16 nodes / block) ---------------
__global__ void __launch_bounds__(256, 2) k_main(
    const float* __restrict__ coors,
    const float* __restrict__ ew1,  const float* __restrict__ eb1,
    const float* __restrict__ ew2,  const float* __restrict__ eb2,
    const float* __restrict__ cw1g, const float* __restrict__ cb1g,
    const float* __restrict__ cw2g, const float* __restrict__ cb2g,
    const float* __restrict__ xw1g, const float* __restrict__ xb1g,
    const float* __restrict__ xw2g, const float* __restrict__ xb2g,
    float* __restrict__ out)
{
    extern __shared__ float smx[];
    float* s_w1q  = smx + O_W1Q;
    float* s_w2q  = smx + O_W2Q;
    float* s_w1r  = smx + O_W1R;
    float* s_cxw1 = smx + O_CXW1;
    float* s_cxb1 = smx + O_CXB1;
    float* s_cxw2 = smx + O_CXW2;
    float* s_b2   = smx + O_B2;
    float* s_base = smx + O_BASE;
    float* s_enc  = smx + O_ENC;
    float* s_m    = smx + O_M;
    float* s_maccw= smx + O_MACW;
    float* s_cacc = smx + O_CACC;
    float* s_geo  = smx + O_GEO;
    int*   s_nb   = (int*)(smx + O_NB);

    int tid = threadIdx.x;
    int lane = tid & 31, wid = tid >> 5;

    // ---- block-level prologue: stage all weights ONCE ----
    for (int idx = tid; idx < 4352; idx += 256) {
        int e4 = idx >> 2, f = idx & 3;
        int qi = e4 / H1P, el = e4 - qi * H1P;
        int r = qi * 4 + f;
        s_w1q[idx] = (el < H1) ? ew1[(size_t)(256 + r) * H1 + el] : 0.f;
    }
    for (int idx = tid; idx < 1088; idx += 256) {
        int el = idx >> 1, f = idx & 1;
        s_w1r[idx] = (el < H1 && f == 0) ? ew1[(size_t)264 * H1 + el] : 0.f;
    }
    for (int idx = tid; idx < 8704; idx += 256) {
        int e4 = idx >> 2, f = idx & 3;
        int cq = e4 / H1P, el = e4 - cq * H1P;
        s_w2q[idx] = (el < H1) ? ew2[(size_t)el * 16 + cq * 4 + f] : 0.f;
    }
    for (int idx = tid; idx < 2048; idx += 256) {
        int p = idx >> 1, w = idx & 1;
        int c = p >> 6, l = p & 63;
        s_cxw1[idx] = w ? xw1g[c * 64 + l] : cw1g[c * 64 + l];
    }
    if (tid < 128) {
        int l = tid >> 1, w = tid & 1;
        s_cxb1[tid] = w ? xb1g[l] : cb1g[l];
        s_cxw2[tid] = w ? xw2g[l] : cw2g[l];
    }
    if (tid < 16) s_b2[tid] = eb2[tid];

    const ulonglong2* w1q64 = (const ulonglong2*)s_w1q;
    const ull* w1r64 = (const ull*)s_w1r;
    const ulonglong2* w2q64 = (const ulonglong2*)s_w2q;
    const ull* b2_64  = (const ull*)s_b2;
    ull* sm64  = (ull*)s_m;
    ull* smd64 = (ull*)(smx + O_MD);
    const ull* cxw1_64 = (const ull*)s_cxw1;
    const ull* cxb1_64 = (const ull*)s_cxb1;
    const ull* cxw2_64 = (const ull*)s_cxw2;

    const ull CP4 = pk2(31.0f / 1451520.0f, 31.0f / 1451520.0f);
    const ull CP3 = pk2(-17.0f / 80640.0f, -17.0f / 80640.0f);
    const ull CP2 = pk2(1.0f / 480.0f, 1.0f / 480.0f);
    const ull CP1 = pk2(-1.0f / 48.0f, -1.0f / 48.0f);
    const ull CP0 = pk2(0.25f, 0.25f);
    const ull CHALF = pk2(0.5f, 0.5f);

    float cb2r = cb2g[0], xb2r = xb2g[0];

    // ---- node loop ----
    #pragma unroll 1
    for (int nn = 0; nn < NODES_PER_BLK; nn++) {
        int bi = blockIdx.x * NODES_PER_BLK + nn;
        int b  = bi >> 11;

        // per-node prologue
        __syncthreads();   // protect previous node's reads before overwrite
        for (int c = tid; c < H1P; c += 256)
            s_base[c] = (c < H1) ? (g_A[(size_t)bi * H1 + c] + eb1[c]) : 0.f;
        if (tid < 4) s_cacc[tid] = 0.f;
        if (tid < 32) {
            float dv = g_dk[(size_t)bi * KK + tid];
            s_enc[tid * 9 + 0] = sinf(dv);
            s_enc[tid * 9 + 1] = sinf(0.5f * dv);
            s_enc[tid * 9 + 2] = sinf(0.25f * dv);
            s_enc[tid * 9 + 3] = sinf(0.125f * dv);
            s_enc[tid * 9 + 4] = cosf(dv);
            s_enc[tid * 9 + 5] = cosf(0.5f * dv);
            s_enc[tid * 9 + 6] = cosf(0.25f * dv);
            s_enc[tid * 9 + 7] = cosf(0.125f * dv);
            s_enc[tid * 9 + 8] = dv;
            s_nb[tid] = g_nbidx[(size_t)bi * KK + tid];
        }
        if (tid < 3) { s_geo[tid] = coors[(size_t)bi * 3 + tid]; s_geo[3 + tid] = g_cm[(size_t)bi * 3 + tid]; }
        __syncthreads();

        float ci0 = s_geo[0], ci1 = s_geo[1], ci2 = s_geo[2];
        float ai0 = s_geo[3], ai1 = s_geo[4], ai2 = s_geo[5];
        const float* cb3 = coors + (size_t)b * NN * 3;
        const float* cmb = g_cm  + (size_t)b * NN * 3;

        float caccl = 0.f;
        float maccr = 0.f;

        #pragma unroll 1
        for (int pass = 0; pass < 2; pass++) {
            int e0 = pass * 16 + wid * 2;
            int j0 = s_nb[e0], j1 = s_nb[e0 + 1];
            const float* bv0 = g_Bv + ((size_t)b * NN + j0) * H1P;
            const float* bv1 = g_Bv + ((size_t)b * NN + j1) * H1P;
            ull e92a[5], e92b[5];
            #pragma unroll
            for (int rp = 0; rp < 5; rp++) {
                float a0 = s_enc[e0 * 9 + 2 * rp];
                float a1 = (2 * rp + 1 < 9) ? s_enc[e0 * 9 + 2 * rp + 1] : 0.f;
                float b0 = s_enc[(e0 + 1) * 9 + 2 * rp];
                float b1 = (2 * rp + 1 < 9) ? s_enc[(e0 + 1) * 9 + 2 * rp + 1] : 0.f;
                e92a[rp] = pk2(a0, a1);
                e92b[rp] = pk2(b0, b1);
            }

            ull q[16];
            #pragma unroll
            for (int i = 0; i < 16; i++) q[i] = 0ULL;

            float bc0 = bv0[lane],      bc1 = bv1[lane];
            float bn0 = bv0[lane + 32], bn1 = bv1[lane + 32];
            #pragma unroll 1
            for (int tt = 0; tt < 17; tt++) {
                int el = tt * 32 + lane;
                float bf0 = bv0[el + 64];
                float bf1 = bv1[el + 64];
                float base = s_base[el];
                ulonglong2 wa = w1q64[el];
                ulonglong2 wb = w1q64[H1P + el];
                ull wc = w1r64[el];
                ull s0 = mul2(e92a[0], wa.x);
                s0 = fma2(e92a[1], wa.y, s0);
                s0 = fma2(e92a[2], wb.x, s0);
                s0 = fma2(e92a[3], wb.y, s0);
                s0 = fma2(e92a[4], wc,   s0);
                ull s1 = mul2(e92b[0], wa.x);
                s1 = fma2(e92b[1], wa.y, s1);
                s1 = fma2(e92b[2], wb.x, s1);
                s1 = fma2(e92b[3], wb.y, s1);
                s1 = fma2(e92b[4], wc,   s1);
                float p0, p1, r0, r1;
                upk2(p0, p1, s0);
                upk2(r0, r1, s1);
                float a0 = base + bc0 + p0 + p1;
                float a1 = base + bc1 + r0 + r1;
                ull h; SILU2(h, pk2(a0, a1));
                float h0, h1; upk2(h0, h1, h);
                ull h0d = pk2(h0, h0), h1d = pk2(h1, h1);
                #pragma unroll
                for (int cq = 0; cq < 4; cq++) {
                    ulonglong2 w2 = w2q64[cq * H1P + el];
                    q[2 * cq]     = fma2(h0d, w2.x, q[2 * cq]);
                    q[2 * cq + 1] = fma2(h0d, w2.y, q[2 * cq + 1]);
                    q[8 + 2 * cq]     = fma2(h1d, w2.x, q[8 + 2 * cq]);
                    q[8 + 2 * cq + 1] = fma2(h1d, w2.y, q[8 + 2 * cq + 1]);
                }
                bc0 = bn0; bc1 = bn1; bn0 = bf0; bn1 = bf1;
            }

            rstep64<16, 8>(q, lane);
            rstep64<8, 4>(q, lane);
            rstep64<4, 2>(q, lane);
            rstep64<2, 1>(q, lane);
            q[0] = add2(q[0], shflx64(q[0], 1));

            {
                int idx = (lane >> 1) & 15;
                int e = idx >> 3, c2 = idx & 7;
                ull mb; SILU2(mb, add2(q[0], b2_64[c2]));
                if ((lane & 1) == 0) {
                    sm64[wid * 16 + e * 8 + c2] = mb;
                    float m0, m1; upk2(m0, m1, mb);
                    smd64[wid * 32 + e * 16 + 2 * c2]     = pk2(m0, m0);
                    smd64[wid * 32 + e * 16 + 2 * c2 + 1] = pk2(m1, m1);
                }
            }
            __syncwarp();
            if (lane < 16) maccr += s_m[wid * 32 + lane] + s_m[wid * 32 + 16 + lane];

            #pragma unroll 1
            for (int e = 0; e < 2; e++) {
                const ull* md = smd64 + wid * 32 + e * 16;
                ull hP0 = cxb1_64[lane];
                ull hP1 = cxb1_64[lane + 32];
                #pragma unroll
                for (int c = 0; c < 16; c++) {
                    ull mdc = md[c];
                    hP0 = fma2(mdc, cxw1_64[c * 64 + lane],      hP0);
                    hP1 = fma2(mdc, cxw1_64[c * 64 + lane + 32], hP1);
                }
                ull sA, sB;
                SILU2(sA, hP0);
                SILU2(sB, hP1);
                ull tt2 = mul2(sA, cxw2_64[lane]);
                tt2 = fma2(sB, cxw2_64[lane + 32], tt2);
                #pragma unroll
                for (int off = 16; off > 0; off >>= 1)
                    tt2 = add2(tt2, shflx64(tt2, off));
                float cw, xw; upk2(cw, xw, tt2);
                cw += cb2r; xw += xb2r;

                int j = (e == 0) ? j0 : j1;
                float cj0 = cb3[3 * j], cj1 = cb3[3 * j + 1], cj2 = cb3[3 * j + 2];
                float bj0 = cmb[3 * j], bj1 = cmb[3 * j + 1], bj2 = cmb[3 * j + 2];
                float rr, xx;
                if (lane == 0)      { rr = ci0 - cj0; xx = ai1 * bj2 - ai2 * bj1; }
                else if (lane == 1) { rr = ci1 - cj1; xx = ai2 * bj0 - ai0 * bj2; }
                else                { rr = ci2 - cj2; xx = ai0 * bj1 - ai1 * bj0; }
                if (lane < 3) caccl = fmaf(cw, rr, fmaf(xw, xx, caccl));
            }
        }
        if (lane < 16) s_maccw[wid * 16 + lane] = maccr;
        if (lane < 3) atomicAdd(&s_cacc[lane], caccl);
        __syncthreads();

        if (tid < 16) {
            float acc = 0.f;
            #pragma unroll
            for (int w = 0; w < 8; w++) acc += s_maccw[w * 16 + tid];
            g_mi[(size_t)bi * 16 + tid] = acc;
        }
        if (tid < 3) {
            float* outc = out + (size_t)NBI * DD;
            outc[(size_t)bi * 3 + tid] = coors[(size_t)bi * 3 + tid] + s_cacc[tid];
        }
    }
}

// ---------------- node MLP: 16 nodes per block -----------------------------------
__global__ void __launch_bounds__(256) k_node(
    const float* __restrict__ feats,
    const float* __restrict__ nw1, const float* __restrict__ nb1,
    const float* __restrict__ nw2, const float* __restrict__ nb2,
    float* __restrict__ out)
{
    __shared__ float s_nw1[16 * 256];
    __shared__ float s_m[16 * 16];
    __shared__ float s_hid[16 * 256];
    int n0 = blockIdx.x * 16;
    int tid = threadIdx.x;

    for (int idx = tid; idx < 4096; idx += 256) {
        int c = idx >> 8, col = idx & 255;
        s_nw1[idx] = nw1[(size_t)(128 + c) * 256 + col];
    }
    s_m[tid] = g_mi[(size_t)n0 * 16 + tid];
    __syncthreads();

    {
        float bcol = nb1[tid];
        #pragma unroll 1
        for (int node = 0; node < 16; node++) {
            float hv = g_NH[(size_t)(n0 + node) * 256 + tid] + bcol;
            #pragma unroll
            for (int c = 0; c < 16; c++)
                hv = fmaf(s_m[node * 16 + c], s_nw1[c * 256 + tid], hv);
            s_hid[node * 256 + tid] = silu_f(hv);
        }
    }
    __syncthreads();

    {
        int col = tid & 127, g = tid >> 7;
        const float* hh = s_hid + g * 8 * 256;
        float acc[8];
        #pragma unroll
        for (int nn = 0; nn < 8; nn++) acc[nn] = 0.f;
        #pragma unroll 4
        for (int k = 0; k < 256; k++) {
            float w = nw2[(size_t)k * 128 + col];
            #pragma unroll
            for (int nn = 0; nn < 8; nn++)
                acc[nn] = fmaf(hh[nn * 256 + k], w, acc[nn]);
        }
        float bb = nb2[col];
        #pragma unroll
        for (int nn = 0; nn < 8; nn++) {
            int node = n0 + g * 8 + nn;
            out[(size_t)node * 128 + col] = acc[nn] + bb + feats[(size_t)node * 128 + col];
        }
    }
}

extern "C" void kernel_launch(void* const* d_in, const int* in_sizes, int n_in,
                              void* d_out, int out_size) {
    const float* feats = (const float*)d_in[0];
    const float* coors = (const float*)d_in[1];
    const float* ew1   = (const float*)d_in[2];
    const float* eb1   = (const float*)d_in[3];
    const float* ew2   = (const float*)d_in[4];
    const float* eb2   = (const float*)d_in[5];
    const float* cw1   = (const float*)d_in[6];
    const float* cb1   = (const float*)d_in[7];
    const float* cw2   = (const float*)d_in[8];
    const float* cb2   = (const float*)d_in[9];
    const float* xw1   = (const float*)d_in[10];
    const float* xb1   = (const float*)d_in[11];
    const float* xw2   = (const float*)d_in[12];
    const float* xb2   = (const float*)d_in[13];
    const float* nw1   = (const float*)d_in[14];
    const float* nb1   = (const float*)d_in[15];
    const float* nw2   = (const float*)d_in[16];
    const float* nb2   = (const float*)d_in[17];
    float* out = (float*)d_out;

    cudaFuncSetAttribute(k_main, cudaFuncAttributeMaxDynamicSharedMemorySize, SMEM_BYTES);
    cudaFuncSetAttribute(k_precomp, cudaFuncAttributeMaxDynamicSharedMemorySize, 65536);

    k_precomp<<<NBI / 64, 256, 65536>>>(feats, ew1, nw1);
    k_mean<<<NB, 256>>>(coors);
    k_topk<<<NBI, 256>>>(coors);
    k_main<<<NBI / NODES_PER_BLK, 256, SMEM_BYTES>>>(coors, ew1, eb1, ew2, eb2,
                                     cw1, cb1, cw2, cb2, xw1, xb1, xw2, xb2, out);
    k_node<<<NBI / 16, 256>>>(feats, nw1, nb1, nw2, nb2, out);
}

// round 9
// speedup vs baseline: 3.0331x; 1.0573x over previous
#include <cuda_runtime.h>
#include <math.h>

#define NB 4
#define NN 2048
#define DD 128
#define KK 32
#define H1 530      // 2*EIN
#define H1P 544     // padded to 17*32
#define NBI (NB*NN) // 8192

typedef unsigned long long ull;
typedef unsigned int uint;

// ---------------- scratch (static device globals; no allocation) ----------------
__device__ float g_A  [NBI * H1];         // feats_i @ W1[0:128]
__device__ float g_Bv [NBI * H1P + 160];  // feats_j @ W1[128:256], padded
__device__ float g_NH [NBI * 256];        // feats   @ node_w1[0:128]
__device__ float g_mi [NBI * 16];         // summed edge messages per node
__device__ float g_cm [NBI * 3];          // mean-centered coords
__device__ int   g_nbidx[NBI * KK];
__device__ float g_dk   [NBI * KK];

// ---------------- packed f32x2 primitives (Blackwell) ---------------------------
__device__ __forceinline__ ull pk2(float lo, float hi) {
    ull r; asm("mov.b64 %0,{%1,%2};" : "=l"(r) : "f"(lo), "f"(hi)); return r;
}
__device__ __forceinline__ void upk2(float& lo, float& hi, ull v) {
    asm("mov.b64 {%0,%1},%2;" : "=f"(lo), "=f"(hi) : "l"(v));
}
__device__ __forceinline__ ull fma2(ull a, ull b, ull c) {
    ull d; asm("fma.rn.f32x2 %0,%1,%2,%3;" : "=l"(d) : "l"(a), "l"(b), "l"(c)); return d;
}
__device__ __forceinline__ ull add2(ull a, ull b) {
    ull d; asm("add.rn.f32x2 %0,%1,%2;" : "=l"(d) : "l"(a), "l"(b)); return d;
}
__device__ __forceinline__ ull mul2(ull a, ull b) {
    ull d; asm("mul.rn.f32x2 %0,%1,%2;" : "=l"(d) : "l"(a), "l"(b)); return d;
}
__device__ __forceinline__ ull shflx64(ull v, int m) {
    uint lo, hi;
    asm("mov.b64 {%0,%1},%2;" : "=r"(lo), "=r"(hi) : "l"(v));
    lo = __shfl_xor_sync(0xffffffffu, lo, m);
    hi = __shfl_xor_sync(0xffffffffu, hi, m);
    ull r; asm("mov.b64 %0,{%1,%2};" : "=l"(r) : "r"(lo), "r"(hi)); return r;
}

// packed silu with exact scalar fallback for |x|>=1 (never taken in practice)
#define SILU2(res, xin) do { \
    ull _x = (xin); \
    ull _x2 = mul2(_x, _x); \
    ull _s = fma2(CP4, _x2, CP3); \
    _s = fma2(_s, _x2, CP2); \
    _s = fma2(_s, _x2, CP1); \
    _s = fma2(_s, _x2, CP0); \
    ull _t = fma2(_x, _s, CHALF); \
    (res) = mul2(_x, _t); \
    float _a, _b; upk2(_a, _b, _x); \
    if (fmaxf(fabsf(_a), fabsf(_b)) >= 1.0f) { \
        float _r0 = _a / (1.0f + __expf(-_a)); \
        float _r1 = _b / (1.0f + __expf(-_b)); \
        (res) = pk2(_r0, _r1); \
    } \
} while (0)

// ---------------- scalar fast SiLU -------------------------
__device__ __forceinline__ float silu_f(float x) {
    float ax = fabsf(x);
    if (ax < 1.0f) {
        float x2 = x * x;
        float s = 31.0f / 1451520.0f;
        s = fmaf(s, x2, -17.0f / 80640.0f);
        s = fmaf(s, x2,  1.0f / 480.0f);
        s = fmaf(s, x2, -1.0f / 48.0f);
        s = fmaf(s, x2,  0.25f);
        return x * fmaf(x, s, 0.5f);
    }
    return x / (1.0f + __expf(-x));
}

// ---------------- merged precompute: A, Bv, NH (packed f32x2 over col pairs) -----
__global__ void __launch_bounds__(256) k_precomp(const float* __restrict__ feats,
                                                 const float* __restrict__ ew1,
                                                 const float* __restrict__ nw1) {
    extern __shared__ float2 sfd[];   // 64 nodes x 128 feats, duplicated pairs
    int n0 = blockIdx.x * 64;
    int t = threadIdx.x;
    for (int idx = t; idx < 64 * 128; idx += 256) {
        float f = feats[(size_t)n0 * 128 + idx];
        sfd[idx] = make_float2(f, f);
    }
    __syncthreads();
    int ng = t >> 5, lane = t & 31;
    const ull* fd = (const ull*)sfd;
    int nb0 = ng * 8;

    #pragma unroll 1
    for (int it = 0; it < 9; it++) {
        int cp = it * 32 + lane;
        int cps = (cp < 265) ? cp : 264;
        ull a[8], bb[8];
        #pragma unroll
        for (int q = 0; q < 8; q++) { a[q] = 0ULL; bb[q] = 0ULL; }
        const float* wbase = ew1 + 2 * cps;
        #pragma unroll 4
        for (int d = 0; d < 128; d++) {
            ull wA = *(const ull*)(wbase + (size_t)d * H1);
            ull wB = *(const ull*)(wbase + (size_t)(128 + d) * H1);
            #pragma unroll
            for (int q = 0; q < 8; q++) {
                ull fv = fd[(nb0 + q) * 128 + d];
                a[q]  = fma2(fv, wA, a[q]);
                bb[q] = fma2(fv, wB, bb[q]);
            }
        }
        if (cp < 265) {
            #pragma unroll
            for (int q = 0; q < 8; q++) {
                int node = n0 + nb0 + q;
                *(ull*)&g_A [(size_t)node * H1  + 2 * cp] = a[q];
                *(ull*)&g_Bv[(size_t)node * H1P + 2 * cp] = bb[q];
            }
        }
    }

    #pragma unroll 1
    for (int it = 0; it < 4; it++) {
        int cp = it * 32 + lane;
        ull a[8];
        #pragma unroll
        for (int q = 0; q < 8; q++) a[q] = 0ULL;
        const float* wbase = nw1 + 2 * cp;
        #pragma unroll 4
        for (int d = 0; d < 128; d++) {
            ull w = *(const ull*)(wbase + (size_t)d * 256);
            #pragma unroll
            for (int q = 0; q < 8; q++)
                a[q] = fma2(fd[(nb0 + q) * 128 + d], w, a[q]);
        }
        #pragma unroll
        for (int q = 0; q < 8; q++)
            *(ull*)&g_NH[(size_t)(n0 + nb0 + q) * 256 + 2 * cp] = a[q];
    }
}

// ---------------- mean-center coords ----------------
__global__ void __launch_bounds__(256) k_mean(const float* __restrict__ coors) {
    int b = blockIdx.x, t = threadIdx.x;
    __shared__ float rx[256], ry[256], rz[256];
    const float* cb = coors + (size_t)b * NN * 3;
    float sx = 0.f, sy = 0.f, sz = 0.f;
    for (int j = t; j < NN; j += 256) {
        sx += cb[3 * j]; sy += cb[3 * j + 1]; sz += cb[3 * j + 2];
    }
    rx[t] = sx; ry[t] = sy; rz[t] = sz;
    __syncthreads();
    for (int s = 128; s > 0; s >>= 1) {
        if (t < s) { rx[t] += rx[t + s]; ry[t] += ry[t + s]; rz[t] += rz[t + s]; }
        __syncthreads();
    }
    float mx = rx[0] * (1.0f / NN), my = ry[0] * (1.0f / NN), mz = rz[0] * (1.0f / NN);
    float* cmb = g_cm + (size_t)b * NN * 3;
    for (int j = t; j < NN; j += 256) {
        cmb[3 * j]     = cb[3 * j]     - mx;
        cmb[3 * j + 1] = cb[3 * j + 1] - my;
        cmb[3 * j + 2] = cb[3 * j + 2] - mz;
    }
}

// ---------------- top-K: binary search on float bit-keys in registers ------------
__global__ void __launch_bounds__(256) k_topk(const float* __restrict__ coors) {
    int bi = blockIdx.x;
    int b  = bi >> 11;
    int t = threadIdx.x, lane = t & 31, wid = t >> 5;
    __shared__ int s_cnt[8];
    __shared__ unsigned s_loS, s_hiS, s_thr;
    __shared__ int s_done, s_sel, s_curmin;

    const float* cb = coors + (size_t)b * NN * 3;
    float cx = coors[(size_t)bi * 3], cy = coors[(size_t)bi * 3 + 1], cz = coors[(size_t)bi * 3 + 2];
    float d[8]; unsigned ud[8];
    #pragma unroll
    for (int i = 0; i < 8; i++) {
        int j = t + i * 256;
        float dx = cx - cb[3 * j], dy = cy - cb[3 * j + 1], dz = cz - cb[3 * j + 2];
        float dv = dx * dx + dy * dy + dz * dz;
        d[i] = dv; ud[i] = __float_as_uint(dv);
    }
    if (t == 0) { s_loS = 0u; s_hiS = 0x7f800000u; s_done = 0; s_sel = 0; s_curmin = -1; }
    __syncthreads();

    #pragma unroll 1
    for (int it = 0; it < 34; it++) {
        unsigned lo = s_loS, hi = s_hiS;
        unsigned mid = lo + ((hi - lo) >> 1);
        int c = 0;
        #pragma unroll
        for (int i = 0; i < 8; i++) c += (ud[i] <= mid) ? 1 : 0;
        #pragma unroll
        for (int off = 16; off; off >>= 1) c += __shfl_xor_sync(0xffffffffu, c, off);
        if (lane == 0) s_cnt[wid] = c;
        __syncthreads();
        if (t == 0) {
            int tot = 0;
            #pragma unroll
            for (int w = 0; w < 8; w++) tot += s_cnt[w];
            if (tot == KK) { s_thr = mid; s_done = 1; }
            else {
                unsigned nlo = lo, nhi = hi;
                if (tot > KK) nhi = mid; else nlo = mid + 1;
                if (nlo >= nhi) { s_thr = nlo; s_done = 2; }
                s_loS = nlo; s_hiS = nhi;
            }
        }
        __syncthreads();
        if (s_done) break;
    }
    unsigned thr = s_thr; int mode = s_done;

    #pragma unroll
    for (int i = 0; i < 8; i++) {
        bool sel = (mode == 1) ? (ud[i] <= thr) : (ud[i] < thr);
        if (sel) {
            int p = atomicAdd(&s_sel, 1);
            g_nbidx[(size_t)bi * KK + p] = t + i * 256;
            g_dk   [(size_t)bi * KK + p] = d[i];
        }
    }
    __syncthreads();
    if (mode == 2) {
        int C = s_sel;
        for (int k = C; k < KK; k++) {
            int prev = s_curmin;
            int cand = 0x7fffffff;
            #pragma unroll
            for (int i = 0; i < 8; i++) {
                int j = t + i * 256;
                if (ud[i] == thr && j > prev && j < cand) cand = j;
            }
            #pragma unroll
            for (int off = 16; off; off >>= 1) {
                int o = __shfl_xor_sync(0xffffffffu, cand, off);
                cand = min(cand, o);
            }
            if (lane == 0) s_cnt[wid] = cand;
            __syncthreads();
            if (t == 0) {
                int mn = s_cnt[0];
                #pragma unroll
                for (int w = 1; w < 8; w++) mn = min(mn, s_cnt[w]);
                g_nbidx[(size_t)bi * KK + k] = mn;
                g_dk   [(size_t)bi * KK + k] = __uint_as_float(thr);
                s_curmin = mn;
            }
            __syncthreads();
        }
    }
}

// ---------------- 64-bit packed reduce-scatter step -----------------------------
template <int MASK, int HALF>
__device__ __forceinline__ void rstep64(ull* q, int lane) {
    bool hi = (lane & MASK) != 0;
    #pragma unroll
    for (int i = 0; i < HALF; i++) {
        ull sent = hi ? q[i] : q[HALF + i];
        ull recv = shflx64(sent, MASK);
        q[i] = add2(hi ? q[HALF + i] : q[i], recv);
    }
}

// ---------------- smem layout (floats) for k_main --------------------------------
#define O_W1Q  0                   // 4352
#define O_W1R  4352                // 1088
#define O_W2Q  5440                // 8704
#define O_CXW1 14144               // 2048
#define O_CXB1 16192               // 128
#define O_CXW2 16320               // 128
#define O_B2   16448               // 16
#define O_EB1  16464               // 544
#define O_BASEW 17008              // 8 warps * 544 = 4352
#define O_ENCW  21360              // 8 warps * 288 = 2304
#define O_M     23664              // 8 warps * 32
#define O_MD    23920              // 8 warps * 64
#define O_NBW   24432              // 8 warps * 32 ints
#define SMEM_FLOATS 24688
#define SMEM_BYTES (SMEM_FLOATS * 4)

// ---------------- fused edge MLP + coord update (warp-per-node) ------------------
__global__ void __launch_bounds__(256, 2) k_main(
    const float* __restrict__ coors,
    const float* __restrict__ ew1,  const float* __restrict__ eb1,
    const float* __restrict__ ew2,  const float* __restrict__ eb2,
    const float* __restrict__ cw1g, const float* __restrict__ cb1g,
    const float* __restrict__ cw2g, const float* __restrict__ cb2g,
    const float* __restrict__ xw1g, const float* __restrict__ xb1g,
    const float* __restrict__ xw2g, const float* __restrict__ xb2g,
    float* __restrict__ out)
{
    extern __shared__ float smx[];
    float* s_w1q  = smx + O_W1Q;
    float* s_w1r  = smx + O_W1R;
    float* s_w2q  = smx + O_W2Q;
    float* s_cxw1 = smx + O_CXW1;
    float* s_cxb1 = smx + O_CXB1;
    float* s_cxw2 = smx + O_CXW2;
    float* s_b2   = smx + O_B2;
    float* s_eb1  = smx + O_EB1;

    int tid = threadIdx.x;
    int lane = tid & 31, wid = tid >> 5;

    // per-warp regions
    float* s_wbase = smx + O_BASEW + wid * 544;
    float* s_wenc  = smx + O_ENCW  + wid * 288;
    float* s_wm    = smx + O_M     + wid * 32;
    ull*   sm64    = (ull*)s_wm;
    ull*   smd64   = (ull*)(smx + O_MD + wid * 64);
    int*   s_wnb   = (int*)(smx + O_NBW) + wid * 32;

    // ---- block-level prologue: stage all weights ONCE ----
    for (int idx = tid; idx < 4352; idx += 256) {
        int e4 = idx >> 2, f = idx & 3;
        int qi = e4 / H1P, el = e4 - qi * H1P;
        int r = qi * 4 + f;
        s_w1q[idx] = (el < H1) ? ew1[(size_t)(256 + r) * H1 + el] : 0.f;
    }
    for (int idx = tid; idx < 1088; idx += 256) {
        int el = idx >> 1, f = idx & 1;
        s_w1r[idx] = (el < H1 && f == 0) ? ew1[(size_t)264 * H1 + el] : 0.f;
    }
    for (int idx = tid; idx < 8704; idx += 256) {
        int e4 = idx >> 2, f = idx & 3;
        int cq = e4 / H1P, el = e4 - cq * H1P;
        s_w2q[idx] = (el < H1) ? ew2[(size_t)el * 16 + cq * 4 + f] : 0.f;
    }
    for (int idx = tid; idx < 2048; idx += 256) {
        int p = idx >> 1, w = idx & 1;
        int c = p >> 6, l = p & 63;
        s_cxw1[idx] = w ? xw1g[c * 64 + l] : cw1g[c * 64 + l];
    }
    if (tid < 128) {
        int l = tid >> 1, w = tid & 1;
        s_cxb1[tid] = w ? xb1g[l] : cb1g[l];
        s_cxw2[tid] = w ? xw2g[l] : cw2g[l];
    }
    if (tid < 16) s_b2[tid] = eb2[tid];
    for (int idx = tid; idx < 544; idx += 256)
        s_eb1[idx] = (idx < H1) ? eb1[idx] : 0.f;
    __syncthreads();   // the ONLY block barrier

    const ulonglong2* w1q64 = (const ulonglong2*)s_w1q;
    const ull* w1r64 = (const ull*)s_w1r;
    const ulonglong2* w2q64 = (const ulonglong2*)s_w2q;
    const ull* b2_64  = (const ull*)s_b2;
    const ull* cxw1_64 = (const ull*)s_cxw1;
    const ull* cxb1_64 = (const ull*)s_cxb1;
    const ull* cxw2_64 = (const ull*)s_cxw2;

    const ull CP4 = pk2(31.0f / 1451520.0f, 31.0f / 1451520.0f);
    const ull CP3 = pk2(-17.0f / 80640.0f, -17.0f / 80640.0f);
    const ull CP2 = pk2(1.0f / 480.0f, 1.0f / 480.0f);
    const ull CP1 = pk2(-1.0f / 48.0f, -1.0f / 48.0f);
    const ull CP0 = pk2(0.25f, 0.25f);
    const ull CHALF = pk2(0.5f, 0.5f);

    float cb2r = cb2g[0], xb2r = xb2g[0];

    // ---- warp-independent node loop: 4 consecutive nodes per warp ----
    int bi0 = (blockIdx.x * 8 + wid) * 4;

    #pragma unroll 1
    for (int kk = 0; kk < 4; kk++) {
        int bi = bi0 + kk;
        int b  = bi >> 11;

        // per-node warp-local prologue
        for (int c = lane; c < H1P; c += 32)
            s_wbase[c] = (c < H1) ? (g_A[(size_t)bi * H1 + c] + s_eb1[c]) : 0.f;
        {
            float dv = g_dk[(size_t)bi * KK + lane];
            s_wenc[lane * 9 + 0] = sinf(dv);
            s_wenc[lane * 9 + 1] = sinf(0.5f * dv);
            s_wenc[lane * 9 + 2] = sinf(0.25f * dv);
            s_wenc[lane * 9 + 3] = sinf(0.125f * dv);
            s_wenc[lane * 9 + 4] = cosf(dv);
            s_wenc[lane * 9 + 5] = cosf(0.5f * dv);
            s_wenc[lane * 9 + 6] = cosf(0.25f * dv);
            s_wenc[lane * 9 + 7] = cosf(0.125f * dv);
            s_wenc[lane * 9 + 8] = dv;
            s_wnb[lane] = g_nbidx[(size_t)bi * KK + lane];
        }
        float ci0 = coors[(size_t)bi * 3 + 0];
        float ci1 = coors[(size_t)bi * 3 + 1];
        float ci2 = coors[(size_t)bi * 3 + 2];
        float ai0 = g_cm[(size_t)bi * 3 + 0];
        float ai1 = g_cm[(size_t)bi * 3 + 1];
        float ai2 = g_cm[(size_t)bi * 3 + 2];
        const float* cb3 = coors + (size_t)b * NN * 3;
        const float* cmb = g_cm  + (size_t)b * NN * 3;
        __syncwarp();

        float caccl = 0.f;
        float maccr = 0.f;

        #pragma unroll 1
        for (int pass = 0; pass < 16; pass++) {
            int e0 = pass * 2;
            int j0 = s_wnb[e0], j1 = s_wnb[e0 + 1];
            const float* bv0 = g_Bv + ((size_t)b * NN + j0) * H1P;
            const float* bv1 = g_Bv + ((size_t)b * NN + j1) * H1P;
            ull e92a[5], e92b[5];
            #pragma unroll
            for (int rp = 0; rp < 5; rp++) {
                float a0 = s_wenc[e0 * 9 + 2 * rp];
                float a1 = (2 * rp + 1 < 9) ? s_wenc[e0 * 9 + 2 * rp + 1] : 0.f;
                float b0 = s_wenc[(e0 + 1) * 9 + 2 * rp];
                float b1 = (2 * rp + 1 < 9) ? s_wenc[(e0 + 1) * 9 + 2 * rp + 1] : 0.f;
                e92a[rp] = pk2(a0, a1);
                e92b[rp] = pk2(b0, b1);
            }

            ull q[16];
            #pragma unroll
            for (int i = 0; i < 16; i++) q[i] = 0ULL;

            float bc0 = bv0[lane],      bc1 = bv1[lane];
            float bn0 = bv0[lane + 32], bn1 = bv1[lane + 32];
            #pragma unroll 1
            for (int tt = 0; tt < 17; tt++) {
                int el = tt * 32 + lane;
                float bf0 = bv0[el + 64];
                float bf1 = bv1[el + 64];
                float base = s_wbase[el];
                ulonglong2 wa = w1q64[el];
                ulonglong2 wb = w1q64[H1P + el];
                ull wc = w1r64[el];
                ull s0 = mul2(e92a[0], wa.x);
                s0 = fma2(e92a[1], wa.y, s0);
                s0 = fma2(e92a[2], wb.x, s0);
                s0 = fma2(e92a[3], wb.y, s0);
                s0 = fma2(e92a[4], wc,   s0);
                ull s1 = mul2(e92b[0], wa.x);
                s1 = fma2(e92b[1], wa.y, s1);
                s1 = fma2(e92b[2], wb.x, s1);
                s1 = fma2(e92b[3], wb.y, s1);
                s1 = fma2(e92b[4], wc,   s1);
                float p0, p1, r0, r1;
                upk2(p0, p1, s0);
                upk2(r0, r1, s1);
                float a0 = base + bc0 + p0 + p1;
                float a1 = base + bc1 + r0 + r1;
                ull h; SILU2(h, pk2(a0, a1));
                float h0, h1; upk2(h0, h1, h);
                ull h0d = pk2(h0, h0), h1d = pk2(h1, h1);
                #pragma unroll
                for (int cq = 0; cq < 4; cq++) {
                    ulonglong2 w2 = w2q64[cq * H1P + el];
                    q[2 * cq]     = fma2(h0d, w2.x, q[2 * cq]);
                    q[2 * cq + 1] = fma2(h0d, w2.y, q[2 * cq + 1]);
                    q[8 + 2 * cq]     = fma2(h1d, w2.x, q[8 + 2 * cq]);
                    q[8 + 2 * cq + 1] = fma2(h1d, w2.y, q[8 + 2 * cq + 1]);
                }
                bc0 = bn0; bc1 = bn1; bn0 = bf0; bn1 = bf1;
            }

            rstep64<16, 8>(q, lane);
            rstep64<8, 4>(q, lane);
            rstep64<4, 2>(q, lane);
            rstep64<2, 1>(q, lane);
            q[0] = add2(q[0], shflx64(q[0], 1));

            {
                int idx = (lane >> 1) & 15;
                int e = idx >> 3, c2 = idx & 7;
                ull mb; SILU2(mb, add2(q[0], b2_64[c2]));
                if ((lane & 1) == 0) {
                    sm64[e * 8 + c2] = mb;
                    float m0, m1; upk2(m0, m1, mb);
                    smd64[e * 16 + 2 * c2]     = pk2(m0, m0);
                    smd64[e * 16 + 2 * c2 + 1] = pk2(m1, m1);
                }
            }
            __syncwarp();
            if (lane < 16) maccr += s_wm[lane] + s_wm[16 + lane];

            #pragma unroll 1
            for (int e = 0; e < 2; e++) {
                const ull* md = smd64 + e * 16;
                ull hP0 = cxb1_64[lane];
                ull hP1 = cxb1_64[lane + 32];
                #pragma unroll
                for (int c = 0; c < 16; c++) {
                    ull mdc = md[c];
                    hP0 = fma2(mdc, cxw1_64[c * 64 + lane],      hP0);
                    hP1 = fma2(mdc, cxw1_64[c * 64 + lane + 32], hP1);
                }
                ull sA, sB;
                SILU2(sA, hP0);
                SILU2(sB, hP1);
                ull tt2 = mul2(sA, cxw2_64[lane]);
                tt2 = fma2(sB, cxw2_64[lane + 32], tt2);
                #pragma unroll
                for (int off = 16; off > 0; off >>= 1)
                    tt2 = add2(tt2, shflx64(tt2, off));
                float cw, xw; upk2(cw, xw, tt2);
                cw += cb2r; xw += xb2r;

                int j = (e == 0) ? j0 : j1;
                float cj0 = cb3[3 * j], cj1 = cb3[3 * j + 1], cj2 = cb3[3 * j + 2];
                float bj0 = cmb[3 * j], bj1 = cmb[3 * j + 1], bj2 = cmb[3 * j + 2];
                float rr, xx;
                if (lane == 0)      { rr = ci0 - cj0; xx = ai1 * bj2 - ai2 * bj1; }
                else if (lane == 1) { rr = ci1 - cj1; xx = ai2 * bj0 - ai0 * bj2; }
                else                { rr = ci2 - cj2; xx = ai0 * bj1 - ai1 * bj0; }
                if (lane < 3) caccl = fmaf(cw, rr, fmaf(xw, xx, caccl));
            }
        }

        // warp-local epilogue (this warp exclusively owns node bi)
        if (lane < 16) g_mi[(size_t)bi * 16 + lane] = maccr;
        if (lane < 3) {
            float* outc = out + (size_t)NBI * DD;
            outc[(size_t)bi * 3 + lane] = coors[(size_t)bi * 3 + lane] + caccl;
        }
        __syncwarp();
    }
}

// ---------------- node MLP: 16 nodes per block -----------------------------------
__global__ void __launch_bounds__(256) k_node(
    const float* __restrict__ feats,
    const float* __restrict__ nw1, const float* __restrict__ nb1,
    const float* __restrict__ nw2, const float* __restrict__ nb2,
    float* __restrict__ out)
{
    __shared__ float s_nw1[16 * 256];
    __shared__ float s_m[16 * 16];
    __shared__ float s_hid[16 * 256];
    int n0 = blockIdx.x * 16;
    int tid = threadIdx.x;

    for (int idx = tid; idx < 4096; idx += 256) {
        int c = idx >> 8, col = idx & 255;
        s_nw1[idx] = nw1[(size_t)(128 + c) * 256 + col];
    }
    s_m[tid] = g_mi[(size_t)n0 * 16 + tid];
    __syncthreads();

    {
        float bcol = nb1[tid];
        #pragma unroll 1
        for (int node = 0; node < 16; node++) {
            float hv = g_NH[(size_t)(n0 + node) * 256 + tid] + bcol;
            #pragma unroll
            for (int c = 0; c < 16; c++)
                hv = fmaf(s_m[node * 16 + c], s_nw1[c * 256 + tid], hv);
            s_hid[node * 256 + tid] = silu_f(hv);
        }
    }
    __syncthreads();

    {
        int col = tid & 127, g = tid >> 7;
        const float* hh = s_hid + g * 8 * 256;
        float acc[8];
        #pragma unroll
        for (int nn = 0; nn < 8; nn++) acc[nn] = 0.f;
        #pragma unroll 4
        for (int k = 0; k < 256; k++) {
            float w = nw2[(size_t)k * 128 + col];
            #pragma unroll
            for (int nn = 0; nn < 8; nn++)
                acc[nn] = fmaf(hh[nn * 256 + k], w, acc[nn]);
        }
        float bb = nb2[col];
        #pragma unroll
        for (int nn = 0; nn < 8; nn++) {
            int node = n0 + g * 8 + nn;
            out[(size_t)node * 128 + col] = acc[nn] + bb + feats[(size_t)node * 128 + col];
        }
    }
}

extern "C" void kernel_launch(void* const* d_in, const int* in_sizes, int n_in,
                              void* d_out, int out_size) {
    const float* feats = (const float*)d_in[0];
    const float* coors = (const float*)d_in[1];
    const float* ew1   = (const float*)d_in[2];
    const float* eb1   = (const float*)d_in[3];
    const float* ew2   = (const float*)d_in[4];
    const float* eb2   = (const float*)d_in[5];
    const float* cw1   = (const float*)d_in[6];
    const float* cb1   = (const float*)d_in[7];
    const float* cw2   = (const float*)d_in[8];
    const float* cb2   = (const float*)d_in[9];
    const float* xw1   = (const float*)d_in[10];
    const float* xb1   = (const float*)d_in[11];
    const float* xw2   = (const float*)d_in[12];
    const float* xb2   = (const float*)d_in[13];
    const float* nw1   = (const float*)d_in[14];
    const float* nb1   = (const float*)d_in[15];
    const float* nw2   = (const float*)d_in[16];
    const float* nb2   = (const float*)d_in[17];
    float* out = (float*)d_out;

    cudaFuncSetAttribute(k_main, cudaFuncAttributeMaxDynamicSharedMemorySize, SMEM_BYTES);
    cudaFuncSetAttribute(k_precomp, cudaFuncAttributeMaxDynamicSharedMemorySize, 65536);

    k_precomp<<<NBI / 64, 256, 65536>>>(feats, ew1, nw1);
    k_mean<<<NB, 256>>>(coors);
    k_topk<<<NBI, 256>>>(coors);
    k_main<<<NBI / 32, 256, SMEM_BYTES>>>(coors, ew1, eb1, ew2, eb2,
                                     cw1, cb1, cw2, cb2, xw1, xb1, xw2, xb2, out);
    k_node<<<NBI / 16, 256>>>(feats, nw1, nb1, nw2, nb2, out);
}

// round 10
// speedup vs baseline: 3.2827x; 1.0823x over previous
#include <cuda_runtime.h>
#include <math.h>

#define NB 4
#define NN 2048
#define DD 128
#define KK 32
#define H1 530      // 2*EIN
#define H1P 544     // padded to 17*32
#define NBI (NB*NN) // 8192
#define NWARPS 2368 // 148 blocks * 16 warps

typedef unsigned long long ull;
typedef unsigned int uint;

// ---------------- scratch (static device globals; no allocation) ----------------
__device__ float g_A  [NBI * H1];         // feats_i @ W1[0:128]
__device__ float g_Bv [NBI * H1P + 160];  // feats_j @ W1[128:256], padded
__device__ float g_NH [NBI * 256];        // feats   @ node_w1[0:128]
__device__ float g_mi [NBI * 16];         // summed edge messages per node
__device__ float g_cm [NBI * 3];          // mean-centered coords
__device__ int   g_nbidx[NBI * KK];
__device__ float g_dk   [NBI * KK];

// ---------------- packed f32x2 primitives (Blackwell) ---------------------------
__device__ __forceinline__ ull pk2(float lo, float hi) {
    ull r; asm("mov.b64 %0,{%1,%2};" : "=l"(r) : "f"(lo), "f"(hi)); return r;
}
__device__ __forceinline__ void upk2(float& lo, float& hi, ull v) {
    asm("mov.b64 {%0,%1},%2;" : "=f"(lo), "=f"(hi) : "l"(v));
}
__device__ __forceinline__ ull fma2(ull a, ull b, ull c) {
    ull d; asm("fma.rn.f32x2 %0,%1,%2,%3;" : "=l"(d) : "l"(a), "l"(b), "l"(c)); return d;
}
__device__ __forceinline__ ull add2(ull a, ull b) {
    ull d; asm("add.rn.f32x2 %0,%1,%2;" : "=l"(d) : "l"(a), "l"(b)); return d;
}
__device__ __forceinline__ ull mul2(ull a, ull b) {
    ull d; asm("mul.rn.f32x2 %0,%1,%2;" : "=l"(d) : "l"(a), "l"(b)); return d;
}
__device__ __forceinline__ ull shflx64(ull v, int m) {
    uint lo, hi;
    asm("mov.b64 {%0,%1},%2;" : "=r"(lo), "=r"(hi) : "l"(v));
    lo = __shfl_xor_sync(0xffffffffu, lo, m);
    hi = __shfl_xor_sync(0xffffffffu, hi, m);
    ull r; asm("mov.b64 %0,{%1,%2};" : "=l"(r) : "r"(lo), "r"(hi)); return r;
}

// packed silu with exact scalar fallback for |x|>=1 (never taken in practice)
#define SILU2(res, xin) do { \
    ull _x = (xin); \
    ull _x2 = mul2(_x, _x); \
    ull _s = fma2(CP4, _x2, CP3); \
    _s = fma2(_s, _x2, CP2); \
    _s = fma2(_s, _x2, CP1); \
    _s = fma2(_s, _x2, CP0); \
    ull _t = fma2(_x, _s, CHALF); \
    (res) = mul2(_x, _t); \
    float _a, _b; upk2(_a, _b, _x); \
    if (fmaxf(fabsf(_a), fabsf(_b)) >= 1.0f) { \
        float _r0 = _a / (1.0f + __expf(-_a)); \
        float _r1 = _b / (1.0f + __expf(-_b)); \
        (res) = pk2(_r0, _r1); \
    } \
} while (0)

// ---------------- scalar fast SiLU -------------------------
__device__ __forceinline__ float silu_f(float x) {
    float ax = fabsf(x);
    if (ax < 1.0f) {
        float x2 = x * x;
        float s = 31.0f / 1451520.0f;
        s = fmaf(s, x2, -17.0f / 80640.0f);
        s = fmaf(s, x2,  1.0f / 480.0f);
        s = fmaf(s, x2, -1.0f / 48.0f);
        s = fmaf(s, x2,  0.25f);
        return x * fmaf(x, s, 0.5f);
    }
    return x / (1.0f + __expf(-x));
}

// ---------------- merged precompute: A, Bv, NH (packed f32x2 over col pairs) -----
__global__ void __launch_bounds__(256) k_precomp(const float* __restrict__ feats,
                                                 const float* __restrict__ ew1,
                                                 const float* __restrict__ nw1) {
    extern __shared__ float2 sfd[];   // 64 nodes x 128 feats, duplicated pairs
    int n0 = blockIdx.x * 64;
    int t = threadIdx.x;
    for (int idx = t; idx < 64 * 128; idx += 256) {
        float f = feats[(size_t)n0 * 128 + idx];
        sfd[idx] = make_float2(f, f);
    }
    __syncthreads();
    int ng = t >> 5, lane = t & 31;
    const ull* fd = (const ull*)sfd;
    int nb0 = ng * 8;

    #pragma unroll 1
    for (int it = 0; it < 9; it++) {
        int cp = it * 32 + lane;
        int cps = (cp < 265) ? cp : 264;
        ull a[8], bb[8];
        #pragma unroll
        for (int q = 0; q < 8; q++) { a[q] = 0ULL; bb[q] = 0ULL; }
        const float* wbase = ew1 + 2 * cps;
        #pragma unroll 4
        for (int d = 0; d < 128; d++) {
            ull wA = *(const ull*)(wbase + (size_t)d * H1);
            ull wB = *(const ull*)(wbase + (size_t)(128 + d) * H1);
            #pragma unroll
            for (int q = 0; q < 8; q++) {
                ull fv = fd[(nb0 + q) * 128 + d];
                a[q]  = fma2(fv, wA, a[q]);
                bb[q] = fma2(fv, wB, bb[q]);
            }
        }
        if (cp < 265) {
            #pragma unroll
            for (int q = 0; q < 8; q++) {
                int node = n0 + nb0 + q;
                *(ull*)&g_A [(size_t)node * H1  + 2 * cp] = a[q];
                *(ull*)&g_Bv[(size_t)node * H1P + 2 * cp] = bb[q];
            }
        }
    }

    #pragma unroll 1
    for (int it = 0; it < 4; it++) {
        int cp = it * 32 + lane;
        ull a[8];
        #pragma unroll
        for (int q = 0; q < 8; q++) a[q] = 0ULL;
        const float* wbase = nw1 + 2 * cp;
        #pragma unroll 4
        for (int d = 0; d < 128; d++) {
            ull w = *(const ull*)(wbase + (size_t)d * 256);
            #pragma unroll
            for (int q = 0; q < 8; q++)
                a[q] = fma2(fd[(nb0 + q) * 128 + d], w, a[q]);
        }
        #pragma unroll
        for (int q = 0; q < 8; q++)
            *(ull*)&g_NH[(size_t)(n0 + nb0 + q) * 256 + 2 * cp] = a[q];
    }
}

// ---------------- mean-center coords ----------------
__global__ void __launch_bounds__(256) k_mean(const float* __restrict__ coors) {
    int b = blockIdx.x, t = threadIdx.x;
    __shared__ float rx[256], ry[256], rz[256];
    const float* cb = coors + (size_t)b * NN * 3;
    float sx = 0.f, sy = 0.f, sz = 0.f;
    for (int j = t; j < NN; j += 256) {
        sx += cb[3 * j]; sy += cb[3 * j + 1]; sz += cb[3 * j + 2];
    }
    rx[t] = sx; ry[t] = sy; rz[t] = sz;
    __syncthreads();
    for (int s = 128; s > 0; s >>= 1) {
        if (t < s) { rx[t] += rx[t + s]; ry[t] += ry[t + s]; rz[t] += rz[t + s]; }
        __syncthreads();
    }
    float mx = rx[0] * (1.0f / NN), my = ry[0] * (1.0f / NN), mz = rz[0] * (1.0f / NN);
    float* cmb = g_cm + (size_t)b * NN * 3;
    for (int j = t; j < NN; j += 256) {
        cmb[3 * j]     = cb[3 * j]     - mx;
        cmb[3 * j + 1] = cb[3 * j + 1] - my;
        cmb[3 * j + 2] = cb[3 * j + 2] - mz;
    }
}

// ---------------- top-K: binary search on float bit-keys in registers ------------
__global__ void __launch_bounds__(256) k_topk(const float* __restrict__ coors) {
    int bi = blockIdx.x;
    int b  = bi >> 11;
    int t = threadIdx.x, lane = t & 31, wid = t >> 5;
    __shared__ int s_cnt[8];
    __shared__ unsigned s_loS, s_hiS, s_thr;
    __shared__ int s_done, s_sel, s_curmin;

    const float* cb = coors + (size_t)b * NN * 3;
    float cx = coors[(size_t)bi * 3], cy = coors[(size_t)bi * 3 + 1], cz = coors[(size_t)bi * 3 + 2];
    float d[8]; unsigned ud[8];
    #pragma unroll
    for (int i = 0; i < 8; i++) {
        int j = t + i * 256;
        float dx = cx - cb[3 * j], dy = cy - cb[3 * j + 1], dz = cz - cb[3 * j + 2];
        float dv = dx * dx + dy * dy + dz * dz;
        d[i] = dv; ud[i] = __float_as_uint(dv);
    }
    if (t == 0) { s_loS = 0u; s_hiS = 0x7f800000u; s_done = 0; s_sel = 0; s_curmin = -1; }
    __syncthreads();

    #pragma unroll 1
    for (int it = 0; it < 34; it++) {
        unsigned lo = s_loS, hi = s_hiS;
        unsigned mid = lo + ((hi - lo) >> 1);
        int c = 0;
        #pragma unroll
        for (int i = 0; i < 8; i++) c += (ud[i] <= mid) ? 1 : 0;
        #pragma unroll
        for (int off = 16; off; off >>= 1) c += __shfl_xor_sync(0xffffffffu, c, off);
        if (lane == 0) s_cnt[wid] = c;
        __syncthreads();
        if (t == 0) {
            int tot = 0;
            #pragma unroll
            for (int w = 0; w < 8; w++) tot += s_cnt[w];
            if (tot == KK) { s_thr = mid; s_done = 1; }
            else {
                unsigned nlo = lo, nhi = hi;
                if (tot > KK) nhi = mid; else nlo = mid + 1;
                if (nlo >= nhi) { s_thr = nlo; s_done = 2; }
                s_loS = nlo; s_hiS = nhi;
            }
        }
        __syncthreads();
        if (s_done) break;
    }
    unsigned thr = s_thr; int mode = s_done;

    #pragma unroll
    for (int i = 0; i < 8; i++) {
        bool sel = (mode == 1) ? (ud[i] <= thr) : (ud[i] < thr);
        if (sel) {
            int p = atomicAdd(&s_sel, 1);
            g_nbidx[(size_t)bi * KK + p] = t + i * 256;
            g_dk   [(size_t)bi * KK + p] = d[i];
        }
    }
    __syncthreads();
    if (mode == 2) {
        int C = s_sel;
        for (int k = C; k < KK; k++) {
            int prev = s_curmin;
            int cand = 0x7fffffff;
            #pragma unroll
            for (int i = 0; i < 8; i++) {
                int j = t + i * 256;
                if (ud[i] == thr && j > prev && j < cand) cand = j;
            }
            #pragma unroll
            for (int off = 16; off; off >>= 1) {
                int o = __shfl_xor_sync(0xffffffffu, cand, off);
                cand = min(cand, o);
            }
            if (lane == 0) s_cnt[wid] = cand;
            __syncthreads();
            if (t == 0) {
                int mn = s_cnt[0];
                #pragma unroll
                for (int w = 1; w < 8; w++) mn = min(mn, s_cnt[w]);
                g_nbidx[(size_t)bi * KK + k] = mn;
                g_dk   [(size_t)bi * KK + k] = __uint_as_float(thr);
                s_curmin = mn;
            }
            __syncthreads();
        }
    }
}

// ---------------- 64-bit packed reduce-scatter step -----------------------------
template <int MASK, int HALF>
__device__ __forceinline__ void rstep64(ull* q, int lane) {
    bool hi = (lane & MASK) != 0;
    #pragma unroll
    for (int i = 0; i < HALF; i++) {
        ull sent = hi ? q[i] : q[HALF + i];
        ull recv = shflx64(sent, MASK);
        q[i] = add2(hi ? q[HALF + i] : q[i], recv);
    }
}

// ---------------- smem layout (floats) for k_main (16 warps / block) -------------
#define O_W1Q  0                   // 4352
#define O_W1R  4352                // 1088
#define O_W2Q  5440                // 8704
#define O_CXW1 14144               // 2048
#define O_CXB1 16192               // 128
#define O_CXW2 16320               // 128
#define O_B2   16448               // 16
#define O_EB1  16464               // 544
#define O_BASEW 17008              // 16 warps * 544 = 8704
#define O_ENCW  25712              // 16 warps * 288 = 4608
#define O_M     30320              // 16 warps * 32 = 512
#define O_MD    30832              // 16 warps * 64 = 1024
#define O_NBW   31856              // 16 warps * 32 ints = 512
#define SMEM_FLOATS 32368
#define SMEM_BYTES (SMEM_FLOATS * 4)

// ---------------- fused edge MLP + coord update (1 block/SM, warp-per-node) ------
__global__ void __launch_bounds__(512, 1) k_main(
    const float* __restrict__ coors,
    const float* __restrict__ ew1,  const float* __restrict__ eb1,
    const float* __restrict__ ew2,  const float* __restrict__ eb2,
    const float* __restrict__ cw1g, const float* __restrict__ cb1g,
    const float* __restrict__ cw2g, const float* __restrict__ cb2g,
    const float* __restrict__ xw1g, const float* __restrict__ xb1g,
    const float* __restrict__ xw2g, const float* __restrict__ xb2g,
    float* __restrict__ out)
{
    extern __shared__ float smx[];
    float* s_w1q  = smx + O_W1Q;
    float* s_w1r  = smx + O_W1R;
    float* s_w2q  = smx + O_W2Q;
    float* s_cxw1 = smx + O_CXW1;
    float* s_cxb1 = smx + O_CXB1;
    float* s_cxw2 = smx + O_CXW2;
    float* s_b2   = smx + O_B2;
    float* s_eb1  = smx + O_EB1;

    int tid = threadIdx.x;
    int lane = tid & 31, wid = tid >> 5;

    // per-warp regions
    float* s_wbase = smx + O_BASEW + wid * 544;
    float* s_wenc  = smx + O_ENCW  + wid * 288;
    float* s_wm    = smx + O_M     + wid * 32;
    ull*   sm64    = (ull*)s_wm;
    ull*   smd64   = (ull*)(smx + O_MD + wid * 64);
    int*   s_wnb   = (int*)(smx + O_NBW) + wid * 32;

    // ---- block-level prologue: stage all weights ONCE per SM ----
    for (int idx = tid; idx < 4352; idx += 512) {
        int e4 = idx >> 2, f = idx & 3;
        int qi = e4 / H1P, el = e4 - qi * H1P;
        int r = qi * 4 + f;
        s_w1q[idx] = (el < H1) ? ew1[(size_t)(256 + r) * H1 + el] : 0.f;
    }
    for (int idx = tid; idx < 1088; idx += 512) {
        int el = idx >> 1, f = idx & 1;
        s_w1r[idx] = (el < H1 && f == 0) ? ew1[(size_t)264 * H1 + el] : 0.f;
    }
    for (int idx = tid; idx < 8704; idx += 512) {
        int e4 = idx >> 2, f = idx & 3;
        int cq = e4 / H1P, el = e4 - cq * H1P;
        s_w2q[idx] = (el < H1) ? ew2[(size_t)el * 16 + cq * 4 + f] : 0.f;
    }
    for (int idx = tid; idx < 2048; idx += 512) {
        int p = idx >> 1, w = idx & 1;
        int c = p >> 6, l = p & 63;
        s_cxw1[idx] = w ? xw1g[c * 64 + l] : cw1g[c * 64 + l];
    }
    if (tid < 128) {
        int l = tid >> 1, w = tid & 1;
        s_cxb1[tid] = w ? xb1g[l] : cb1g[l];
        s_cxw2[tid] = w ? xw2g[l] : cw2g[l];
    }
    if (tid < 16) s_b2[tid] = eb2[tid];
    for (int idx = tid; idx < 544; idx += 512)
        s_eb1[idx] = (idx < H1) ? eb1[idx] : 0.f;
    __syncthreads();   // the ONLY block barrier

    const ulonglong2* w1q64 = (const ulonglong2*)s_w1q;
    const ull* w1r64 = (const ull*)s_w1r;
    const ulonglong2* w2q64 = (const ulonglong2*)s_w2q;
    const ull* b2_64  = (const ull*)s_b2;
    const ull* cxw1_64 = (const ull*)s_cxw1;
    const ull* cxb1_64 = (const ull*)s_cxb1;
    const ull* cxw2_64 = (const ull*)s_cxw2;

    const ull CP4 = pk2(31.0f / 1451520.0f, 31.0f / 1451520.0f);
    const ull CP3 = pk2(-17.0f / 80640.0f, -17.0f / 80640.0f);
    const ull CP2 = pk2(1.0f / 480.0f, 1.0f / 480.0f);
    const ull CP1 = pk2(-1.0f / 48.0f, -1.0f / 48.0f);
    const ull CP0 = pk2(0.25f, 0.25f);
    const ull CHALF = pk2(0.5f, 0.5f);

    float cb2r = cb2g[0], xb2r = xb2g[0];

    // ---- warp-independent node loop: transposed assignment for balance ----
    // warp rank r = wid*148 + blockIdx.x in [0, 2368); nodes bi = r + k*2368
    int r0 = wid * 148 + blockIdx.x;

    #pragma unroll 1
    for (int kk = 0; kk < 4; kk++) {
        int bi = r0 + kk * NWARPS;
        if (bi >= NBI) break;
        int b  = bi >> 11;

        // per-node warp-local prologue
        for (int c = lane; c < H1P; c += 32)
            s_wbase[c] = (c < H1) ? (g_A[(size_t)bi * H1 + c] + s_eb1[c]) : 0.f;
        {
            float dv = g_dk[(size_t)bi * KK + lane];
            s_wenc[lane * 9 + 0] = sinf(dv);
            s_wenc[lane * 9 + 1] = sinf(0.5f * dv);
            s_wenc[lane * 9 + 2] = sinf(0.25f * dv);
            s_wenc[lane * 9 + 3] = sinf(0.125f * dv);
            s_wenc[lane * 9 + 4] = cosf(dv);
            s_wenc[lane * 9 + 5] = cosf(0.5f * dv);
            s_wenc[lane * 9 + 6] = cosf(0.25f * dv);
            s_wenc[lane * 9 + 7] = cosf(0.125f * dv);
            s_wenc[lane * 9 + 8] = dv;
            s_wnb[lane] = g_nbidx[(size_t)bi * KK + lane];
        }
        float ci0 = coors[(size_t)bi * 3 + 0];
        float ci1 = coors[(size_t)bi * 3 + 1];
        float ci2 = coors[(size_t)bi * 3 + 2];
        float ai0 = g_cm[(size_t)bi * 3 + 0];
        float ai1 = g_cm[(size_t)bi * 3 + 1];
        float ai2 = g_cm[(size_t)bi * 3 + 2];
        const float* cb3 = coors + (size_t)b * NN * 3;
        const float* cmb = g_cm  + (size_t)b * NN * 3;
        __syncwarp();

        float caccl = 0.f;
        float maccr = 0.f;

        #pragma unroll 1
        for (int pass = 0; pass < 16; pass++) {
            int e0 = pass * 2;
            int j0 = s_wnb[e0], j1 = s_wnb[e0 + 1];
            const float* bv0 = g_Bv + ((size_t)b * NN + j0) * H1P;
            const float* bv1 = g_Bv + ((size_t)b * NN + j1) * H1P;
            ull e92a[5], e92b[5];
            #pragma unroll
            for (int rp = 0; rp < 5; rp++) {
                float a0 = s_wenc[e0 * 9 + 2 * rp];
                float a1 = (2 * rp + 1 < 9) ? s_wenc[e0 * 9 + 2 * rp + 1] : 0.f;
                float b0 = s_wenc[(e0 + 1) * 9 + 2 * rp];
                float b1 = (2 * rp + 1 < 9) ? s_wenc[(e0 + 1) * 9 + 2 * rp + 1] : 0.f;
                e92a[rp] = pk2(a0, a1);
                e92b[rp] = pk2(b0, b1);
            }

            ull q[16];
            #pragma unroll
            for (int i = 0; i < 16; i++) q[i] = 0ULL;

            float bc0 = bv0[lane],      bc1 = bv1[lane];
            float bn0 = bv0[lane + 32], bn1 = bv1[lane + 32];
            #pragma unroll 1
            for (int tt = 0; tt < 17; tt++) {
                int el = tt * 32 + lane;
                float bf0 = bv0[el + 64];
                float bf1 = bv1[el + 64];
                float base = s_wbase[el];
                ulonglong2 wa = w1q64[el];
                ulonglong2 wb = w1q64[H1P + el];
                ull wc = w1r64[el];
                ull s0 = mul2(e92a[0], wa.x);
                s0 = fma2(e92a[1], wa.y, s0);
                s0 = fma2(e92a[2], wb.x, s0);
                s0 = fma2(e92a[3], wb.y, s0);
                s0 = fma2(e92a[4], wc,   s0);
                ull s1 = mul2(e92b[0], wa.x);
                s1 = fma2(e92b[1], wa.y, s1);
                s1 = fma2(e92b[2], wb.x, s1);
                s1 = fma2(e92b[3], wb.y, s1);
                s1 = fma2(e92b[4], wc,   s1);
                float p0, p1, rr0, rr1;
                upk2(p0, p1, s0);
                upk2(rr0, rr1, s1);
                float a0 = base + bc0 + p0 + p1;
                float a1 = base + bc1 + rr0 + rr1;
                ull h; SILU2(h, pk2(a0, a1));
                float h0, h1; upk2(h0, h1, h);
                ull h0d = pk2(h0, h0), h1d = pk2(h1, h1);
                #pragma unroll
                for (int cq = 0; cq < 4; cq++) {
                    ulonglong2 w2 = w2q64[cq * H1P + el];
                    q[2 * cq]     = fma2(h0d, w2.x, q[2 * cq]);
                    q[2 * cq + 1] = fma2(h0d, w2.y, q[2 * cq + 1]);
                    q[8 + 2 * cq]     = fma2(h1d, w2.x, q[8 + 2 * cq]);
                    q[8 + 2 * cq + 1] = fma2(h1d, w2.y, q[8 + 2 * cq + 1]);
                }
                bc0 = bn0; bc1 = bn1; bn0 = bf0; bn1 = bf1;
            }

            rstep64<16, 8>(q, lane);
            rstep64<8, 4>(q, lane);
            rstep64<4, 2>(q, lane);
            rstep64<2, 1>(q, lane);
            q[0] = add2(q[0], shflx64(q[0], 1));

            {
                int idx = (lane >> 1) & 15;
                int e = idx >> 3, c2 = idx & 7;
                ull mb; SILU2(mb, add2(q[0], b2_64[c2]));
                if ((lane & 1) == 0) {
                    sm64[e * 8 + c2] = mb;
                    float m0, m1; upk2(m0, m1, mb);
                    smd64[e * 16 + 2 * c2]     = pk2(m0, m0);
                    smd64[e * 16 + 2 * c2 + 1] = pk2(m1, m1);
                }
            }
            __syncwarp();
            if (lane < 16) maccr += s_wm[lane] + s_wm[16 + lane];

            #pragma unroll 1
            for (int e = 0; e < 2; e++) {
                const ull* md = smd64 + e * 16;
                ull hP0 = cxb1_64[lane];
                ull hP1 = cxb1_64[lane + 32];
                #pragma unroll
                for (int c = 0; c < 16; c++) {
                    ull mdc = md[c];
                    hP0 = fma2(mdc, cxw1_64[c * 64 + lane],      hP0);
                    hP1 = fma2(mdc, cxw1_64[c * 64 + lane + 32], hP1);
                }
                ull sA, sB;
                SILU2(sA, hP0);
                SILU2(sB, hP1);
                ull tt2 = mul2(sA, cxw2_64[lane]);
                tt2 = fma2(sB, cxw2_64[lane + 32], tt2);
                #pragma unroll
                for (int off = 16; off > 0; off >>= 1)
                    tt2 = add2(tt2, shflx64(tt2, off));
                float cw, xw; upk2(cw, xw, tt2);
                cw += cb2r; xw += xb2r;

                int j = (e == 0) ? j0 : j1;
                float cj0 = cb3[3 * j], cj1 = cb3[3 * j + 1], cj2 = cb3[3 * j + 2];
                float bj0 = cmb[3 * j], bj1 = cmb[3 * j + 1], bj2 = cmb[3 * j + 2];
                float rr, xx;
                if (lane == 0)      { rr = ci0 - cj0; xx = ai1 * bj2 - ai2 * bj1; }
                else if (lane == 1) { rr = ci1 - cj1; xx = ai2 * bj0 - ai0 * bj2; }
                else                { rr = ci2 - cj2; xx = ai0 * bj1 - ai1 * bj0; }
                if (lane < 3) caccl = fmaf(cw, rr, fmaf(xw, xx, caccl));
            }
        }

        // warp-local epilogue (this warp exclusively owns node bi)
        if (lane < 16) g_mi[(size_t)bi * 16 + lane] = maccr;
        if (lane < 3) {
            float* outc = out + (size_t)NBI * DD;
            outc[(size_t)bi * 3 + lane] = coors[(size_t)bi * 3 + lane] + caccl;
        }
        __syncwarp();
    }
}

// ---------------- node MLP: 16 nodes per block -----------------------------------
__global__ void __launch_bounds__(256) k_node(
    const float* __restrict__ feats,
    const float* __restrict__ nw1, const float* __restrict__ nb1,
    const float* __restrict__ nw2, const float* __restrict__ nb2,
    float* __restrict__ out)
{
    __shared__ float s_nw1[16 * 256];
    __shared__ float s_m[16 * 16];
    __shared__ float s_hid[16 * 256];
    int n0 = blockIdx.x * 16;
    int tid = threadIdx.x;

    for (int idx = tid; idx < 4096; idx += 256) {
        int c = idx >> 8, col = idx & 255;
        s_nw1[idx] = nw1[(size_t)(128 + c) * 256 + col];
    }
    s_m[tid] = g_mi[(size_t)n0 * 16 + tid];
    __syncthreads();

    {
        float bcol = nb1[tid];
        #pragma unroll 1
        for (int node = 0; node < 16; node++) {
            float hv = g_NH[(size_t)(n0 + node) * 256 + tid] + bcol;
            #pragma unroll
            for (int c = 0; c < 16; c++)
                hv = fmaf(s_m[node * 16 + c], s_nw1[c * 256 + tid], hv);
            s_hid[node * 256 + tid] = silu_f(hv);
        }
    }
    __syncthreads();

    {
        int col = tid & 127, g = tid >> 7;
        const float* hh = s_hid + g * 8 * 256;
        float acc[8];
        #pragma unroll
        for (int nn = 0; nn < 8; nn++) acc[nn] = 0.f;
        #pragma unroll 4
        for (int k = 0; k < 256; k++) {
            float w = nw2[(size_t)k * 128 + col];
            #pragma unroll
            for (int nn = 0; nn < 8; nn++)
                acc[nn] = fmaf(hh[nn * 256 + k], w, acc[nn]);
        }
        float bb = nb2[col];
        #pragma unroll
        for (int nn = 0; nn < 8; nn++) {
            int node = n0 + g * 8 + nn;
            out[(size_t)node * 128 + col] = acc[nn] + bb + feats[(size_t)node * 128 + col];
        }
    }
}

extern "C" void kernel_launch(void* const* d_in, const int* in_sizes, int n_in,
                              void* d_out, int out_size) {
    const float* feats = (const float*)d_in[0];
    const float* coors = (const float*)d_in[1];
    const float* ew1   = (const float*)d_in[2];
    const float* eb1   = (const float*)d_in[3];
    const float* ew2   = (const float*)d_in[4];
    const float* eb2   = (const float*)d_in[5];
    const float* cw1   = (const float*)d_in[6];
    const float* cb1   = (const float*)d_in[7];
    const float* cw2   = (const float*)d_in[8];
    const float* cb2   = (const float*)d_in[9];
    const float* xw1   = (const float*)d_in[10];
    const float* xb1   = (const float*)d_in[11];
    const float* xw2   = (const float*)d_in[12];
    const float* xb2   = (const float*)d_in[13];
    const float* nw1   = (const float*)d_in[14];
    const float* nb1   = (const float*)d_in[15];
    const float* nw2   = (const float*)d_in[16];
    const float* nb2   = (const float*)d_in[17];
    float* out = (float*)d_out;

    cudaFuncSetAttribute(k_main, cudaFuncAttributeMaxDynamicSharedMemorySize, SMEM_BYTES);
    cudaFuncSetAttribute(k_precomp, cudaFuncAttributeMaxDynamicSharedMemorySize, 65536);

    k_precomp<<<NBI / 64, 256, 65536>>>(feats, ew1, nw1);
    k_mean<<<NB, 256>>>(coors);
    k_topk<<<NBI, 256>>>(coors);
    k_main<<<148, 512, SMEM_BYTES>>>(coors, ew1, eb1, ew2, eb2,
                                     cw1, cb1, cw2, cb2, xw1, xb1, xw2, xb2, out);
    k_node<<<NBI / 16, 256>>>(feats, nw1, nb1, nw2, nb2, out);
}